// round 11
// baseline (speedup 1.0000x reference)
#include <cuda_runtime.h>
#include <cuda_bf16.h>
#include <cstdint>
#include <math.h>

#define S_LEN 2048
#define HIDN  4096
#define NHEAD 32
#define HDIM  128

// ------------------------------ scratch (static, allocation-free) ----------
__device__ float g_Q[S_LEN * HIDN];
__device__ float g_K[S_LEN * HIDN];
__device__ float g_V[S_LEN * HIDN];
__device__ float g_A[S_LEN * HIDN];
__device__ float g_cs[S_LEN * 64];
__device__ float g_sn[S_LEN * 64];

// ------------------------------ helpers ------------------------------------
__device__ __forceinline__ uint32_t smem_u32(const void* p) {
    uint32_t a;
    asm("{ .reg .u64 t; cvta.to.shared.u64 t, %1; cvt.u32.u64 %0, t; }"
        : "=r"(a) : "l"(p));
    return a;
}

#define LDSM_X4(r, addr)                                                      \
    asm volatile("ldmatrix.sync.aligned.m8n8.x4.shared.b16 {%0,%1,%2,%3}, [%4];" \
        : "=r"((r)[0]), "=r"((r)[1]), "=r"((r)[2]), "=r"((r)[3]) : "r"(addr))

#define MMA_BF16(d, a, b0, b1)                                                \
    asm volatile("mma.sync.aligned.m16n8k16.row.col.f32.bf16.bf16.f32 "       \
        "{%0,%1,%2,%3}, {%4,%5,%6,%7}, {%8,%9}, {%0,%1,%2,%3};"               \
        : "+f"((d)[0]), "+f"((d)[1]), "+f"((d)[2]), "+f"((d)[3])              \
        : "r"((a)[0]), "r"((a)[1]), "r"((a)[2]), "r"((a)[3]),                 \
          "r"(b0), "r"(b1))

__device__ __forceinline__ void cvt_hilo(float4 v, uint2& h, uint2& l)
{
    __nv_bfloat16 h0 = __float2bfloat16(v.x), h1 = __float2bfloat16(v.y);
    __nv_bfloat16 h2 = __float2bfloat16(v.z), h3 = __float2bfloat16(v.w);
    __nv_bfloat16 l0 = __float2bfloat16(v.x - __bfloat162float(h0));
    __nv_bfloat16 l1 = __float2bfloat16(v.y - __bfloat162float(h1));
    __nv_bfloat16 l2 = __float2bfloat16(v.z - __bfloat162float(h2));
    __nv_bfloat16 l3 = __float2bfloat16(v.w - __bfloat162float(h3));
    h.x = (uint32_t)*(unsigned short*)&h0 | ((uint32_t)*(unsigned short*)&h1 << 16);
    h.y = (uint32_t)*(unsigned short*)&h2 | ((uint32_t)*(unsigned short*)&h3 << 16);
    l.x = (uint32_t)*(unsigned short*)&l0 | ((uint32_t)*(unsigned short*)&l1 << 16);
    l.y = (uint32_t)*(unsigned short*)&l2 | ((uint32_t)*(unsigned short*)&l3 << 16);
}

// ------------------------------ HMMA bf16x3 GEMM ----------------------------
// C[m,n] = sum_k A[m,k] * B[n,k]  (fp32 in/out, bf16 hi/lo split on the fly)
// CTA: 128x128 tile, 512 thr = 16 warps (4m x 4n), warp tile 32x32.
// (4 warps per SMSP scheduler vs 2 before -> hide ldsm/mma latency.)
// K-chunks of 32 (two k16 steps), double-buffered smem, pitch 40 bf16.
#define KC    32
#define PITCH 40
#define TILE_ELEMS (128 * PITCH)          // bf16 per tile
#define TILE_BYTES (TILE_ELEMS * 2)       // 10240
#define BUF_BYTES  (4 * TILE_BYTES)       // Ah, Al, Bh, Bl
#define GEMM_SMEM  (2 * BUF_BYTES)        // 81920

__global__ void __launch_bounds__(512, 1)
gemm_mma(const float* __restrict__ A, const float* __restrict__ B,
         float* __restrict__ C)
{
    extern __shared__ char smraw[];
    __nv_bfloat16* sh = (__nv_bfloat16*)smraw;
    const uint32_t smb = smem_u32(sh);

    const int tid  = threadIdx.x;
    const int lane = tid & 31;
    const int wid  = tid >> 5;
    const int wm   = wid & 3;        // m quarter (32 rows)
    const int wn   = wid >> 2;       // n quarter (32 cols)
    const int m0   = blockIdx.y << 7;
    const int n0   = blockIdx.x << 7;

    float acc[2][4][4];
#pragma unroll
    for (int i = 0; i < 2; i++)
#pragma unroll
        for (int j = 0; j < 4; j++)
#pragma unroll
            for (int r = 0; r < 4; r++) acc[i][j][r] = 0.f;

    // loader staging: 2 float4 for A rows, 2 for B rows per chunk
    float4 reg[4];

    auto ldg_chunk = [&](int k0) {
#pragma unroll
        for (int i = 0; i < 2; i++) {
            const int idx = tid + i * 512;          // 0..1023
            const int row = idx >> 3;
            const int col = (idx & 7) << 2;
            reg[i]     = *(const float4*)(A + (size_t)(m0 + row) * HIDN + k0 + col);
            reg[2 + i] = *(const float4*)(B + (size_t)(n0 + row) * HIDN + k0 + col);
        }
    };
    auto sts_chunk = [&](int b) {
        __nv_bfloat16* Ah = sh + b * 4 * TILE_ELEMS;
        __nv_bfloat16* Al = Ah + TILE_ELEMS;
        __nv_bfloat16* Bh = Ah + 2 * TILE_ELEMS;
        __nv_bfloat16* Bl = Ah + 3 * TILE_ELEMS;
#pragma unroll
        for (int i = 0; i < 2; i++) {
            const int idx = tid + i * 512;
            const int row = idx >> 3;
            const int col = (idx & 7) << 2;
            uint2 h, l;
            cvt_hilo(reg[i], h, l);
            *(uint2*)&Ah[row * PITCH + col] = h;
            *(uint2*)&Al[row * PITCH + col] = l;
            cvt_hilo(reg[2 + i], h, l);
            *(uint2*)&Bh[row * PITCH + col] = h;
            *(uint2*)&Bl[row * PITCH + col] = l;
        }
    };

    auto compute = [&](int b) {
        const uint32_t base = smb + b * BUF_BYTES;
        const uint32_t Ah = base;
        const uint32_t Al = base + TILE_BYTES;
        const uint32_t Bh = base + 2 * TILE_BYTES;
        const uint32_t Bl = base + 3 * TILE_BYTES;

        // lane-derived ldmatrix source coordinates
        const int arow = wm * 32 + (lane & 15);
        const int brow = wn * 32 + ((lane >> 4) << 3) + (lane & 7);
#pragma unroll
        for (int ks = 0; ks < 2; ks++) {
            const int acol = ks * 16 + ((lane >> 4) << 3);
            const int bcol = ks * 16 + (((lane >> 3) & 1) << 3);

            uint32_t ah[2][4], al[2][4], bh[2][4], bl[2][4];
#pragma unroll
            for (int ms = 0; ms < 2; ms++) {
                const uint32_t off = ((arow + ms * 16) * PITCH + acol) * 2;
                LDSM_X4(ah[ms], Ah + off);
                LDSM_X4(al[ms], Al + off);
            }
#pragma unroll
            for (int p = 0; p < 2; p++) {
                const uint32_t off = ((brow + p * 16) * PITCH + bcol) * 2;
                LDSM_X4(bh[p], Bh + off);
                LDSM_X4(bl[p], Bl + off);
            }
#pragma unroll
            for (int ms = 0; ms < 2; ms++)
#pragma unroll
                for (int p = 0; p < 2; p++)
#pragma unroll
                    for (int hf = 0; hf < 2; hf++) {
                        const int ns = p * 2 + hf;
                        MMA_BF16(acc[ms][ns], ah[ms], bh[p][hf * 2], bh[p][hf * 2 + 1]);
                        MMA_BF16(acc[ms][ns], ah[ms], bl[p][hf * 2], bl[p][hf * 2 + 1]);
                        MMA_BF16(acc[ms][ns], al[ms], bh[p][hf * 2], bh[p][hf * 2 + 1]);
                    }
        }
    };

    ldg_chunk(0);
    sts_chunk(0);
    __syncthreads();

    const int NCHUNK = HIDN / KC;   // 128
    for (int c = 0; c < NCHUNK; c++) {
        if (c + 1 < NCHUNK) ldg_chunk((c + 1) * KC);
        compute(c & 1);
        if (c + 1 < NCHUNK) sts_chunk((c + 1) & 1);
        __syncthreads();
    }

    // epilogue: D frag rows t/4 (+8), cols (t%4)*2 (+1)
    const int er = lane >> 2;
    const int ec = (lane & 3) << 1;
#pragma unroll
    for (int ms = 0; ms < 2; ms++) {
        const int row = m0 + wm * 32 + ms * 16 + er;
#pragma unroll
        for (int ns = 0; ns < 4; ns++) {
            const int col = n0 + wn * 32 + ns * 8 + ec;
            *(float2*)(C + (size_t)row * HIDN + col) =
                make_float2(acc[ms][ns][0], acc[ms][ns][1]);
            *(float2*)(C + (size_t)(row + 8) * HIDN + col) =
                make_float2(acc[ms][ns][2], acc[ms][ns][3]);
        }
    }
}

// ------------------------------ rope ---------------------------------------
__global__ void __launch_bounds__(256)
rope_table()
{
    const int idx = blockIdx.x * blockDim.x + threadIdx.x;
    const int j = idx & 63;
    const int s = idx >> 6;
    const float invf = (float)pow(10000.0, -(double)(2 * j) / 128.0);
    const float ang  = (float)s * invf;
    g_cs[idx] = (float)cos((double)ang);
    g_sn[idx] = (float)sin((double)ang);
}

__global__ void __launch_bounds__(256)
rope_halfsplit()
{
    const int idx = blockIdx.x * blockDim.x + threadIdx.x;
    const int j = idx & 63;
    const int h = (idx >> 6) & 31;
    const int s = idx >> 11;
    const float cs = g_cs[(s << 6) + j];
    const float sn = g_sn[(s << 6) + j];
    const size_t base = (size_t)s * HIDN + h * HDIM + j;
    const float q0 = g_Q[base], q1 = g_Q[base + 64];
    g_Q[base]      = q0 * cs - q1 * sn;
    g_Q[base + 64] = q1 * cs + q0 * sn;
    const float k0 = g_K[base], k1 = g_K[base + 64];
    g_K[base]      = k0 * cs - k1 * sn;
    g_K[base + 64] = k1 * cs + k0 * sn;
}

// ------------------------------ flash attention (fp32) ---------------------
#define QP 129
#define VP 132
#define FLASH2_SMEM_FLOATS (64 * QP * 2 + 64 * VP + 64 * 64 + 192)

__global__ void __launch_bounds__(256)
flash2()
{
    extern __shared__ float sm[];
    float* Qs = sm;
    float* Ks = Qs + 64 * QP;
    float* Vs = Ks + 64 * QP;
    float* Ps = Vs + 64 * VP;
    float* mrow = Ps + 64 * 64;
    float* lrow = mrow + 64;
    float* crow = lrow + 64;

    const int h  = blockIdx.y;
    const int q0 = blockIdx.x << 6;
    const int tid = threadIdx.x;
    const int tc = tid & 15;
    const int tr = tid >> 4;

    const float* Qg = g_Q + (size_t)q0 * HIDN + h * HDIM;
    for (int t = tid; t < 64 * 32; t += 256) {
        const int r = t >> 5;
        const int c = (t & 31) << 2;
        float4 v = *(const float4*)(Qg + (size_t)r * HIDN + c);
        Qs[r * QP + c + 0] = v.x; Qs[r * QP + c + 1] = v.y;
        Qs[r * QP + c + 2] = v.z; Qs[r * QP + c + 3] = v.w;
    }
    if (tid < 64) { mrow[tid] = -1e30f; lrow[tid] = 0.f; }

    float o[4][8];
#pragma unroll
    for (int i = 0; i < 4; i++)
#pragma unroll
        for (int j = 0; j < 8; j++) o[i][j] = 0.f;

    for (int k0 = 0; k0 <= q0; k0 += 64) {
        __syncthreads();
        const float* Kg = g_K + (size_t)k0 * HIDN + h * HDIM;
        const float* Vg = g_V + (size_t)k0 * HIDN + h * HDIM;
        for (int t = tid; t < 64 * 32; t += 256) {
            const int r = t >> 5;
            const int c = (t & 31) << 2;
            float4 v = *(const float4*)(Kg + (size_t)r * HIDN + c);
            Ks[r * QP + c + 0] = v.x; Ks[r * QP + c + 1] = v.y;
            Ks[r * QP + c + 2] = v.z; Ks[r * QP + c + 3] = v.w;
            float4 w = *(const float4*)(Vg + (size_t)r * HIDN + c);
            *(float4*)&Vs[r * VP + c] = w;
        }
        __syncthreads();

        float s4[4][4];
#pragma unroll
        for (int i = 0; i < 4; i++)
#pragma unroll
            for (int j = 0; j < 4; j++) s4[i][j] = 0.f;

#pragma unroll 4
        for (int d = 0; d < 128; d++) {
            float qv[4], kv[4];
#pragma unroll
            for (int i = 0; i < 4; i++) qv[i] = Qs[((tr << 2) + i) * QP + d];
#pragma unroll
            for (int j = 0; j < 4; j++) kv[j] = Ks[((tc << 2) + j) * QP + d];
#pragma unroll
            for (int i = 0; i < 4; i++)
#pragma unroll
                for (int j = 0; j < 4; j++)
                    s4[i][j] = fmaf(qv[i], kv[j], s4[i][j]);
        }

        const float sc = 0.08838834764831845f;
        const bool diag = (k0 == q0);
#pragma unroll
        for (int i = 0; i < 4; i++) {
            const int qi = (tr << 2) + i;
            float sv[4];
            float rmax = -1e30f;
#pragma unroll
            for (int j = 0; j < 4; j++) {
                float v = s4[i][j] * sc;
                if (diag && ((tc << 2) + j > qi)) v = -1e30f;
                sv[j] = v;
                rmax = fmaxf(rmax, v);
            }
            rmax = fmaxf(rmax, __shfl_xor_sync(0xffffffffu, rmax, 8));
            rmax = fmaxf(rmax, __shfl_xor_sync(0xffffffffu, rmax, 4));
            rmax = fmaxf(rmax, __shfl_xor_sync(0xffffffffu, rmax, 2));
            rmax = fmaxf(rmax, __shfl_xor_sync(0xffffffffu, rmax, 1));
            const float mo = mrow[qi];
            const float mn = fmaxf(mo, rmax);
            float rs = 0.f;
#pragma unroll
            for (int j = 0; j < 4; j++) {
                const float p = __expf(sv[j] - mn);
                Ps[qi * 64 + (tc << 2) + j] = p;
                rs += p;
            }
            rs += __shfl_xor_sync(0xffffffffu, rs, 8);
            rs += __shfl_xor_sync(0xffffffffu, rs, 4);
            rs += __shfl_xor_sync(0xffffffffu, rs, 2);
            rs += __shfl_xor_sync(0xffffffffu, rs, 1);
            if (tc == 0) {
                const float cr = __expf(mo - mn);
                crow[qi] = cr;
                lrow[qi] = lrow[qi] * cr + rs;
                mrow[qi] = mn;
            }
        }
        __syncthreads();

#pragma unroll
        for (int i = 0; i < 4; i++) {
            const float cr = crow[(tr << 2) + i];
#pragma unroll
            for (int j = 0; j < 8; j++) o[i][j] *= cr;
        }
#pragma unroll 2
        for (int n = 0; n < 64; n++) {
            float4 v0 = *(const float4*)&Vs[n * VP + (tc << 3)];
            float4 v1 = *(const float4*)&Vs[n * VP + (tc << 3) + 4];
            const float vv[8] = {v0.x, v0.y, v0.z, v0.w, v1.x, v1.y, v1.z, v1.w};
#pragma unroll
            for (int i = 0; i < 4; i++) {
                const float p = Ps[((tr << 2) + i) * 64 + n];
#pragma unroll
                for (int j = 0; j < 8; j++)
                    o[i][j] = fmaf(p, vv[j], o[i][j]);
            }
        }
    }

#pragma unroll
    for (int i = 0; i < 4; i++) {
        const int qi = (tr << 2) + i;
        const float rl = 1.0f / lrow[qi];
        float* ap = g_A + (size_t)(q0 + qi) * HIDN + h * HDIM + (tc << 3);
        *(float4*)ap       = make_float4(o[i][0] * rl, o[i][1] * rl, o[i][2] * rl, o[i][3] * rl);
        *(float4*)(ap + 4) = make_float4(o[i][4] * rl, o[i][5] * rl, o[i][6] * rl, o[i][7] * rl);
    }
}

// ---------------------------------------------------------------------------
extern "C" void kernel_launch(void* const* d_in, const int* in_sizes, int n_in,
                              void* d_out, int out_size)
{
    const float* X  = (const float*)d_in[0];
    const float* Wq = (const float*)d_in[2];
    const float* Wk = (const float*)d_in[3];
    const float* Wv = (const float*)d_in[4];
    const float* Wo = (const float*)d_in[5];
    float* out = (float*)d_out;

    float *dQ, *dK, *dV, *dA;
    cudaGetSymbolAddress((void**)&dQ, g_Q);
    cudaGetSymbolAddress((void**)&dK, g_K);
    cudaGetSymbolAddress((void**)&dV, g_V);
    cudaGetSymbolAddress((void**)&dA, g_A);

    rope_table<<<(S_LEN * 64) / 256, 256>>>();

    cudaFuncSetAttribute(gemm_mma, cudaFuncAttributeMaxDynamicSharedMemorySize, GEMM_SMEM);
    const dim3 gg(HIDN / 128, S_LEN / 128);
    gemm_mma<<<gg, 512, GEMM_SMEM>>>(X, Wq, dQ);
    gemm_mma<<<gg, 512, GEMM_SMEM>>>(X, Wk, dK);
    gemm_mma<<<gg, 512, GEMM_SMEM>>>(X, Wv, dV);

    rope_halfsplit<<<(S_LEN * NHEAD * 64) / 256, 256>>>();

    const int fsmem = FLASH2_SMEM_FLOATS * (int)sizeof(float);
    cudaFuncSetAttribute(flash2, cudaFuncAttributeMaxDynamicSharedMemorySize, fsmem);
    flash2<<<dim3(S_LEN / 64, NHEAD), 256, fsmem>>>();

    gemm_mma<<<gg, 512, GEMM_SMEM>>>(dA, Wo, out);
}

// round 12
// speedup vs baseline: 1.2305x; 1.2305x over previous
#include <cuda_runtime.h>
#include <cuda_bf16.h>
#include <cstdint>
#include <math.h>

#define S_LEN 2048
#define HIDN  4096
#define NHEAD 32
#define HDIM  128

// ------------------------------ scratch (static, allocation-free) ----------
__device__ float g_Q[S_LEN * HIDN];
__device__ float g_K[S_LEN * HIDN];
__device__ float g_V[S_LEN * HIDN];
__device__ float g_A[S_LEN * HIDN];
__device__ float g_cs[S_LEN * 64];
__device__ float g_sn[S_LEN * 64];

// ------------------------------ helpers ------------------------------------
__device__ __forceinline__ uint32_t smem_u32(const void* p) {
    uint32_t a;
    asm("{ .reg .u64 t; cvta.to.shared.u64 t, %1; cvt.u32.u64 %0, t; }"
        : "=r"(a) : "l"(p));
    return a;
}

#define LDSM_X4(r, addr)                                                      \
    asm volatile("ldmatrix.sync.aligned.m8n8.x4.shared.b16 {%0,%1,%2,%3}, [%4];" \
        : "=r"((r)[0]), "=r"((r)[1]), "=r"((r)[2]), "=r"((r)[3]) : "r"(addr))

#define MMA_BF16(d, a, b0, b1)                                                \
    asm volatile("mma.sync.aligned.m16n8k16.row.col.f32.bf16.bf16.f32 "       \
        "{%0,%1,%2,%3}, {%4,%5,%6,%7}, {%8,%9}, {%0,%1,%2,%3};"               \
        : "+f"((d)[0]), "+f"((d)[1]), "+f"((d)[2]), "+f"((d)[3])              \
        : "r"((a)[0]), "r"((a)[1]), "r"((a)[2]), "r"((a)[3]),                 \
          "r"(b0), "r"(b1))

__device__ __forceinline__ void cvt_hilo(float4 v, uint2& h, uint2& l)
{
    __nv_bfloat16 h0 = __float2bfloat16(v.x), h1 = __float2bfloat16(v.y);
    __nv_bfloat16 h2 = __float2bfloat16(v.z), h3 = __float2bfloat16(v.w);
    __nv_bfloat16 l0 = __float2bfloat16(v.x - __bfloat162float(h0));
    __nv_bfloat16 l1 = __float2bfloat16(v.y - __bfloat162float(h1));
    __nv_bfloat16 l2 = __float2bfloat16(v.z - __bfloat162float(h2));
    __nv_bfloat16 l3 = __float2bfloat16(v.w - __bfloat162float(h3));
    h.x = (uint32_t)*(unsigned short*)&h0 | ((uint32_t)*(unsigned short*)&h1 << 16);
    h.y = (uint32_t)*(unsigned short*)&h2 | ((uint32_t)*(unsigned short*)&h3 << 16);
    l.x = (uint32_t)*(unsigned short*)&l0 | ((uint32_t)*(unsigned short*)&l1 << 16);
    l.y = (uint32_t)*(unsigned short*)&l2 | ((uint32_t)*(unsigned short*)&l3 << 16);
}

// ------------------------------ HMMA bf16x3 GEMM ----------------------------
// C[m,n] = sum_k A[m,k] * B[n,k]  (fp32 in/out, bf16 hi/lo split on the fly)
// CTA: 128x128 tile, 128 thr = 4 warps (2m x 2n), warp tile 64x64.
// 6 MMA per ldsm.x4 (vs 4 in r10, 3 in r11) -> less smem traffic per MMA.
// KC=16 (one k16 step per chunk), double-buffered, 2 CTAs/SM for overlap.
#define KC    16
#define PITCH 24
#define TILE_ELEMS (128 * PITCH)          // bf16 per tile
#define TILE_BYTES (TILE_ELEMS * 2)       // 6144
#define BUF_BYTES  (4 * TILE_BYTES)       // Ah, Al, Bh, Bl = 24576
#define GEMM_SMEM  (2 * BUF_BYTES)        // 49152

__global__ void __launch_bounds__(128, 2)
gemm_mma(const float* __restrict__ A, const float* __restrict__ B,
         float* __restrict__ C)
{
    extern __shared__ char smraw[];
    __nv_bfloat16* sh = (__nv_bfloat16*)smraw;
    const uint32_t smb = smem_u32(sh);

    const int tid  = threadIdx.x;
    const int lane = tid & 31;
    const int wid  = tid >> 5;
    const int wm   = wid & 1;        // m half (64 rows)
    const int wn   = wid >> 1;       // n half (64 cols)
    const int m0   = blockIdx.y << 7;
    const int n0   = blockIdx.x << 7;

    float acc[4][8][4];
#pragma unroll
    for (int i = 0; i < 4; i++)
#pragma unroll
        for (int j = 0; j < 8; j++)
#pragma unroll
            for (int r = 0; r < 4; r++) acc[i][j][r] = 0.f;

    // loader staging: 4 float4 for A, 4 for B per chunk (128 rows x 16 cols)
    float4 reg[8];

    auto ldg_chunk = [&](int k0) {
#pragma unroll
        for (int i = 0; i < 4; i++) {
            const int idx = tid + i * 128;          // 0..511
            const int row = idx >> 2;
            const int col = (idx & 3) << 2;
            reg[i]     = *(const float4*)(A + (size_t)(m0 + row) * HIDN + k0 + col);
            reg[4 + i] = *(const float4*)(B + (size_t)(n0 + row) * HIDN + k0 + col);
        }
    };
    auto sts_chunk = [&](int b) {
        __nv_bfloat16* Ah = sh + b * 4 * TILE_ELEMS;
        __nv_bfloat16* Al = Ah + TILE_ELEMS;
        __nv_bfloat16* Bh = Ah + 2 * TILE_ELEMS;
        __nv_bfloat16* Bl = Ah + 3 * TILE_ELEMS;
#pragma unroll
        for (int i = 0; i < 4; i++) {
            const int idx = tid + i * 128;
            const int row = idx >> 2;
            const int col = (idx & 3) << 2;
            uint2 h, l;
            cvt_hilo(reg[i], h, l);
            *(uint2*)&Ah[row * PITCH + col] = h;
            *(uint2*)&Al[row * PITCH + col] = l;
            cvt_hilo(reg[4 + i], h, l);
            *(uint2*)&Bh[row * PITCH + col] = h;
            *(uint2*)&Bl[row * PITCH + col] = l;
        }
    };

    auto compute = [&](int b) {
        const uint32_t base = smb + b * BUF_BYTES;
        const uint32_t Ah = base;
        const uint32_t Al = base + TILE_BYTES;
        const uint32_t Bh = base + 2 * TILE_BYTES;
        const uint32_t Bl = base + 3 * TILE_BYTES;

        const int arow = wm * 64 + (lane & 15);
        const int acol = (lane >> 4) << 3;
        const int brow = wn * 64 + ((lane >> 4) << 3) + (lane & 7);
        const int bcol = ((lane >> 3) & 1) << 3;

        uint32_t ah[4][4], al[4][4];
#pragma unroll
        for (int ms = 0; ms < 4; ms++) {
            const uint32_t off = ((arow + ms * 16) * PITCH + acol) * 2;
            LDSM_X4(ah[ms], Ah + off);
            LDSM_X4(al[ms], Al + off);
        }
#pragma unroll
        for (int p = 0; p < 4; p++) {
            uint32_t bh[4], bl[4];
            const uint32_t off = ((brow + p * 16) * PITCH + bcol) * 2;
            LDSM_X4(bh, Bh + off);
            LDSM_X4(bl, Bl + off);
#pragma unroll
            for (int ms = 0; ms < 4; ms++)
#pragma unroll
                for (int hf = 0; hf < 2; hf++) {
                    const int ns = p * 2 + hf;
                    MMA_BF16(acc[ms][ns], ah[ms], bh[hf * 2], bh[hf * 2 + 1]);
                    MMA_BF16(acc[ms][ns], ah[ms], bl[hf * 2], bl[hf * 2 + 1]);
                    MMA_BF16(acc[ms][ns], al[ms], bh[hf * 2], bh[hf * 2 + 1]);
                }
        }
    };

    ldg_chunk(0);
    sts_chunk(0);
    __syncthreads();

    const int NCHUNK = HIDN / KC;   // 256
    for (int c = 0; c < NCHUNK; c++) {
        if (c + 1 < NCHUNK) ldg_chunk((c + 1) * KC);
        compute(c & 1);
        if (c + 1 < NCHUNK) sts_chunk((c + 1) & 1);
        __syncthreads();
    }

    // epilogue: D frag rows t/4 (+8), cols (t%4)*2 (+1)
    const int er = lane >> 2;
    const int ec = (lane & 3) << 1;
#pragma unroll
    for (int ms = 0; ms < 4; ms++) {
        const int row = m0 + wm * 64 + ms * 16 + er;
#pragma unroll
        for (int ns = 0; ns < 8; ns++) {
            const int col = n0 + wn * 64 + ns * 8 + ec;
            *(float2*)(C + (size_t)row * HIDN + col) =
                make_float2(acc[ms][ns][0], acc[ms][ns][1]);
            *(float2*)(C + (size_t)(row + 8) * HIDN + col) =
                make_float2(acc[ms][ns][2], acc[ms][ns][3]);
        }
    }
}

// ------------------------------ rope ---------------------------------------
__global__ void __launch_bounds__(256)
rope_table()
{
    const int idx = blockIdx.x * blockDim.x + threadIdx.x;
    const int j = idx & 63;
    const int s = idx >> 6;
    const float invf = (float)pow(10000.0, -(double)(2 * j) / 128.0);
    const float ang  = (float)s * invf;
    g_cs[idx] = (float)cos((double)ang);
    g_sn[idx] = (float)sin((double)ang);
}

__global__ void __launch_bounds__(256)
rope_halfsplit()
{
    const int idx = blockIdx.x * blockDim.x + threadIdx.x;
    const int j = idx & 63;
    const int h = (idx >> 6) & 31;
    const int s = idx >> 11;
    const float cs = g_cs[(s << 6) + j];
    const float sn = g_sn[(s << 6) + j];
    const size_t base = (size_t)s * HIDN + h * HDIM + j;
    const float q0 = g_Q[base], q1 = g_Q[base + 64];
    g_Q[base]      = q0 * cs - q1 * sn;
    g_Q[base + 64] = q1 * cs + q0 * sn;
    const float k0 = g_K[base], k1 = g_K[base + 64];
    g_K[base]      = k0 * cs - k1 * sn;
    g_K[base + 64] = k1 * cs + k0 * sn;
}

// ------------------------------ flash attention (fp32) ---------------------
#define QP 129
#define VP 132
#define FLASH2_SMEM_FLOATS (64 * QP * 2 + 64 * VP + 64 * 64 + 192)

__global__ void __launch_bounds__(256)
flash2()
{
    extern __shared__ float sm[];
    float* Qs = sm;
    float* Ks = Qs + 64 * QP;
    float* Vs = Ks + 64 * QP;
    float* Ps = Vs + 64 * VP;
    float* mrow = Ps + 64 * 64;
    float* lrow = mrow + 64;
    float* crow = lrow + 64;

    const int h  = blockIdx.y;
    const int q0 = blockIdx.x << 6;
    const int tid = threadIdx.x;
    const int tc = tid & 15;
    const int tr = tid >> 4;

    const float* Qg = g_Q + (size_t)q0 * HIDN + h * HDIM;
    for (int t = tid; t < 64 * 32; t += 256) {
        const int r = t >> 5;
        const int c = (t & 31) << 2;
        float4 v = *(const float4*)(Qg + (size_t)r * HIDN + c);
        Qs[r * QP + c + 0] = v.x; Qs[r * QP + c + 1] = v.y;
        Qs[r * QP + c + 2] = v.z; Qs[r * QP + c + 3] = v.w;
    }
    if (tid < 64) { mrow[tid] = -1e30f; lrow[tid] = 0.f; }

    float o[4][8];
#pragma unroll
    for (int i = 0; i < 4; i++)
#pragma unroll
        for (int j = 0; j < 8; j++) o[i][j] = 0.f;

    for (int k0 = 0; k0 <= q0; k0 += 64) {
        __syncthreads();
        const float* Kg = g_K + (size_t)k0 * HIDN + h * HDIM;
        const float* Vg = g_V + (size_t)k0 * HIDN + h * HDIM;
        for (int t = tid; t < 64 * 32; t += 256) {
            const int r = t >> 5;
            const int c = (t & 31) << 2;
            float4 v = *(const float4*)(Kg + (size_t)r * HIDN + c);
            Ks[r * QP + c + 0] = v.x; Ks[r * QP + c + 1] = v.y;
            Ks[r * QP + c + 2] = v.z; Ks[r * QP + c + 3] = v.w;
            float4 w = *(const float4*)(Vg + (size_t)r * HIDN + c);
            *(float4*)&Vs[r * VP + c] = w;
        }
        __syncthreads();

        float s4[4][4];
#pragma unroll
        for (int i = 0; i < 4; i++)
#pragma unroll
            for (int j = 0; j < 4; j++) s4[i][j] = 0.f;

#pragma unroll 4
        for (int d = 0; d < 128; d++) {
            float qv[4], kv[4];
#pragma unroll
            for (int i = 0; i < 4; i++) qv[i] = Qs[((tr << 2) + i) * QP + d];
#pragma unroll
            for (int j = 0; j < 4; j++) kv[j] = Ks[((tc << 2) + j) * QP + d];
#pragma unroll
            for (int i = 0; i < 4; i++)
#pragma unroll
                for (int j = 0; j < 4; j++)
                    s4[i][j] = fmaf(qv[i], kv[j], s4[i][j]);
        }

        const float sc = 0.08838834764831845f;
        const bool diag = (k0 == q0);
#pragma unroll
        for (int i = 0; i < 4; i++) {
            const int qi = (tr << 2) + i;
            float sv[4];
            float rmax = -1e30f;
#pragma unroll
            for (int j = 0; j < 4; j++) {
                float v = s4[i][j] * sc;
                if (diag && ((tc << 2) + j > qi)) v = -1e30f;
                sv[j] = v;
                rmax = fmaxf(rmax, v);
            }
            rmax = fmaxf(rmax, __shfl_xor_sync(0xffffffffu, rmax, 8));
            rmax = fmaxf(rmax, __shfl_xor_sync(0xffffffffu, rmax, 4));
            rmax = fmaxf(rmax, __shfl_xor_sync(0xffffffffu, rmax, 2));
            rmax = fmaxf(rmax, __shfl_xor_sync(0xffffffffu, rmax, 1));
            const float mo = mrow[qi];
            const float mn = fmaxf(mo, rmax);
            float rs = 0.f;
#pragma unroll
            for (int j = 0; j < 4; j++) {
                const float p = __expf(sv[j] - mn);
                Ps[qi * 64 + (tc << 2) + j] = p;
                rs += p;
            }
            rs += __shfl_xor_sync(0xffffffffu, rs, 8);
            rs += __shfl_xor_sync(0xffffffffu, rs, 4);
            rs += __shfl_xor_sync(0xffffffffu, rs, 2);
            rs += __shfl_xor_sync(0xffffffffu, rs, 1);
            if (tc == 0) {
                const float cr = __expf(mo - mn);
                crow[qi] = cr;
                lrow[qi] = lrow[qi] * cr + rs;
                mrow[qi] = mn;
            }
        }
        __syncthreads();

#pragma unroll
        for (int i = 0; i < 4; i++) {
            const float cr = crow[(tr << 2) + i];
#pragma unroll
            for (int j = 0; j < 8; j++) o[i][j] *= cr;
        }
#pragma unroll 2
        for (int n = 0; n < 64; n++) {
            float4 v0 = *(const float4*)&Vs[n * VP + (tc << 3)];
            float4 v1 = *(const float4*)&Vs[n * VP + (tc << 3) + 4];
            const float vv[8] = {v0.x, v0.y, v0.z, v0.w, v1.x, v1.y, v1.z, v1.w};
#pragma unroll
            for (int i = 0; i < 4; i++) {
                const float p = Ps[((tr << 2) + i) * 64 + n];
#pragma unroll
                for (int j = 0; j < 8; j++)
                    o[i][j] = fmaf(p, vv[j], o[i][j]);
            }
        }
    }

#pragma unroll
    for (int i = 0; i < 4; i++) {
        const int qi = (tr << 2) + i;
        const float rl = 1.0f / lrow[qi];
        float* ap = g_A + (size_t)(q0 + qi) * HIDN + h * HDIM + (tc << 3);
        *(float4*)ap       = make_float4(o[i][0] * rl, o[i][1] * rl, o[i][2] * rl, o[i][3] * rl);
        *(float4*)(ap + 4) = make_float4(o[i][4] * rl, o[i][5] * rl, o[i][6] * rl, o[i][7] * rl);
    }
}

// ---------------------------------------------------------------------------
extern "C" void kernel_launch(void* const* d_in, const int* in_sizes, int n_in,
                              void* d_out, int out_size)
{
    const float* X  = (const float*)d_in[0];
    const float* Wq = (const float*)d_in[2];
    const float* Wk = (const float*)d_in[3];
    const float* Wv = (const float*)d_in[4];
    const float* Wo = (const float*)d_in[5];
    float* out = (float*)d_out;

    float *dQ, *dK, *dV, *dA;
    cudaGetSymbolAddress((void**)&dQ, g_Q);
    cudaGetSymbolAddress((void**)&dK, g_K);
    cudaGetSymbolAddress((void**)&dV, g_V);
    cudaGetSymbolAddress((void**)&dA, g_A);

    rope_table<<<(S_LEN * 64) / 256, 256>>>();

    cudaFuncSetAttribute(gemm_mma, cudaFuncAttributeMaxDynamicSharedMemorySize, GEMM_SMEM);
    const dim3 gg(HIDN / 128, S_LEN / 128);
    gemm_mma<<<gg, 128, GEMM_SMEM>>>(X, Wq, dQ);
    gemm_mma<<<gg, 128, GEMM_SMEM>>>(X, Wk, dK);
    gemm_mma<<<gg, 128, GEMM_SMEM>>>(X, Wv, dV);

    rope_halfsplit<<<(S_LEN * NHEAD * 64) / 256, 256>>>();

    const int fsmem = FLASH2_SMEM_FLOATS * (int)sizeof(float);
    cudaFuncSetAttribute(flash2, cudaFuncAttributeMaxDynamicSharedMemorySize, fsmem);
    flash2<<<dim3(S_LEN / 64, NHEAD), 256, fsmem>>>();

    gemm_mma<<<gg, 128, GEMM_SMEM>>>(dA, Wo, out);
}

// round 13
// speedup vs baseline: 1.7475x; 1.4201x over previous
#include <cuda_runtime.h>
#include <cuda_bf16.h>
#include <cstdint>
#include <math.h>

#define S_LEN 2048
#define HIDN  4096
#define NHEAD 32
#define HDIM  128

// ------------------------------ scratch (static, allocation-free) ----------
__device__ float g_Q[S_LEN * HIDN];
__device__ float g_K[S_LEN * HIDN];
__device__ float g_V[S_LEN * HIDN];
__device__ float g_A[S_LEN * HIDN];
__device__ float g_cs[S_LEN * 64];
__device__ float g_sn[S_LEN * 64];

// bf16 hi/lo operands for flash (Q/K roped, layout [s][4096]; V transposed [h][d][s])
__device__ __nv_bfloat16 g_Qh[S_LEN * HIDN], g_Ql[S_LEN * HIDN];
__device__ __nv_bfloat16 g_Kh[S_LEN * HIDN], g_Kl[S_LEN * HIDN];
__device__ __nv_bfloat16 g_Vth[NHEAD * HDIM * S_LEN], g_Vtl[NHEAD * HDIM * S_LEN];

// ------------------------------ helpers ------------------------------------
__device__ __forceinline__ uint32_t smem_u32(const void* p) {
    uint32_t a;
    asm("{ .reg .u64 t; cvta.to.shared.u64 t, %1; cvt.u32.u64 %0, t; }"
        : "=r"(a) : "l"(p));
    return a;
}

#define LDSM_X4(r, addr)                                                      \
    asm volatile("ldmatrix.sync.aligned.m8n8.x4.shared.b16 {%0,%1,%2,%3}, [%4];" \
        : "=r"((r)[0]), "=r"((r)[1]), "=r"((r)[2]), "=r"((r)[3]) : "r"(addr))

#define MMA_BF16(d, a, b0, b1)                                                \
    asm volatile("mma.sync.aligned.m16n8k16.row.col.f32.bf16.bf16.f32 "       \
        "{%0,%1,%2,%3}, {%4,%5,%6,%7}, {%8,%9}, {%0,%1,%2,%3};"               \
        : "+f"((d)[0]), "+f"((d)[1]), "+f"((d)[2]), "+f"((d)[3])              \
        : "r"((a)[0]), "r"((a)[1]), "r"((a)[2]), "r"((a)[3]),                 \
          "r"(b0), "r"(b1))

__device__ __forceinline__ void cvt_hilo(float4 v, uint2& h, uint2& l)
{
    __nv_bfloat16 h0 = __float2bfloat16(v.x), h1 = __float2bfloat16(v.y);
    __nv_bfloat16 h2 = __float2bfloat16(v.z), h3 = __float2bfloat16(v.w);
    __nv_bfloat16 l0 = __float2bfloat16(v.x - __bfloat162float(h0));
    __nv_bfloat16 l1 = __float2bfloat16(v.y - __bfloat162float(h1));
    __nv_bfloat16 l2 = __float2bfloat16(v.z - __bfloat162float(h2));
    __nv_bfloat16 l3 = __float2bfloat16(v.w - __bfloat162float(h3));
    h.x = (uint32_t)*(unsigned short*)&h0 | ((uint32_t)*(unsigned short*)&h1 << 16);
    h.y = (uint32_t)*(unsigned short*)&h2 | ((uint32_t)*(unsigned short*)&h3 << 16);
    l.x = (uint32_t)*(unsigned short*)&l0 | ((uint32_t)*(unsigned short*)&l1 << 16);
    l.y = (uint32_t)*(unsigned short*)&l2 | ((uint32_t)*(unsigned short*)&l3 << 16);
}

// ------------------------------ HMMA bf16x3 GEMM (r12, validated) ----------
#define KC    16
#define PITCH 24
#define TILE_ELEMS (128 * PITCH)
#define TILE_BYTES (TILE_ELEMS * 2)
#define BUF_BYTES  (4 * TILE_BYTES)
#define GEMM_SMEM  (2 * BUF_BYTES)

__global__ void __launch_bounds__(128, 2)
gemm_mma(const float* __restrict__ A, const float* __restrict__ B,
         float* __restrict__ C)
{
    extern __shared__ char smraw[];
    __nv_bfloat16* sh = (__nv_bfloat16*)smraw;
    const uint32_t smb = smem_u32(sh);

    const int tid  = threadIdx.x;
    const int lane = tid & 31;
    const int wid  = tid >> 5;
    const int wm   = wid & 1;
    const int wn   = wid >> 1;
    const int m0   = blockIdx.y << 7;
    const int n0   = blockIdx.x << 7;

    float acc[4][8][4];
#pragma unroll
    for (int i = 0; i < 4; i++)
#pragma unroll
        for (int j = 0; j < 8; j++)
#pragma unroll
            for (int r = 0; r < 4; r++) acc[i][j][r] = 0.f;

    float4 reg[8];

    auto ldg_chunk = [&](int k0) {
#pragma unroll
        for (int i = 0; i < 4; i++) {
            const int idx = tid + i * 128;
            const int row = idx >> 2;
            const int col = (idx & 3) << 2;
            reg[i]     = *(const float4*)(A + (size_t)(m0 + row) * HIDN + k0 + col);
            reg[4 + i] = *(const float4*)(B + (size_t)(n0 + row) * HIDN + k0 + col);
        }
    };
    auto sts_chunk = [&](int b) {
        __nv_bfloat16* Ah = sh + b * 4 * TILE_ELEMS;
        __nv_bfloat16* Al = Ah + TILE_ELEMS;
        __nv_bfloat16* Bh = Ah + 2 * TILE_ELEMS;
        __nv_bfloat16* Bl = Ah + 3 * TILE_ELEMS;
#pragma unroll
        for (int i = 0; i < 4; i++) {
            const int idx = tid + i * 128;
            const int row = idx >> 2;
            const int col = (idx & 3) << 2;
            uint2 h, l;
            cvt_hilo(reg[i], h, l);
            *(uint2*)&Ah[row * PITCH + col] = h;
            *(uint2*)&Al[row * PITCH + col] = l;
            cvt_hilo(reg[4 + i], h, l);
            *(uint2*)&Bh[row * PITCH + col] = h;
            *(uint2*)&Bl[row * PITCH + col] = l;
        }
    };

    auto compute = [&](int b) {
        const uint32_t base = smb + b * BUF_BYTES;
        const uint32_t Ah = base;
        const uint32_t Al = base + TILE_BYTES;
        const uint32_t Bh = base + 2 * TILE_BYTES;
        const uint32_t Bl = base + 3 * TILE_BYTES;

        const int arow = wm * 64 + (lane & 15);
        const int acol = (lane >> 4) << 3;
        const int brow = wn * 64 + ((lane >> 4) << 3) + (lane & 7);
        const int bcol = ((lane >> 3) & 1) << 3;

        uint32_t ah[4][4], al[4][4];
#pragma unroll
        for (int ms = 0; ms < 4; ms++) {
            const uint32_t off = ((arow + ms * 16) * PITCH + acol) * 2;
            LDSM_X4(ah[ms], Ah + off);
            LDSM_X4(al[ms], Al + off);
        }
#pragma unroll
        for (int p = 0; p < 4; p++) {
            uint32_t bh[4], bl[4];
            const uint32_t off = ((brow + p * 16) * PITCH + bcol) * 2;
            LDSM_X4(bh, Bh + off);
            LDSM_X4(bl, Bl + off);
#pragma unroll
            for (int ms = 0; ms < 4; ms++)
#pragma unroll
                for (int hf = 0; hf < 2; hf++) {
                    const int ns = p * 2 + hf;
                    MMA_BF16(acc[ms][ns], ah[ms], bh[hf * 2], bh[hf * 2 + 1]);
                    MMA_BF16(acc[ms][ns], ah[ms], bl[hf * 2], bl[hf * 2 + 1]);
                    MMA_BF16(acc[ms][ns], al[ms], bh[hf * 2], bh[hf * 2 + 1]);
                }
        }
    };

    ldg_chunk(0);
    sts_chunk(0);
    __syncthreads();

    const int NCHUNK = HIDN / KC;
    for (int c = 0; c < NCHUNK; c++) {
        if (c + 1 < NCHUNK) ldg_chunk((c + 1) * KC);
        compute(c & 1);
        if (c + 1 < NCHUNK) sts_chunk((c + 1) & 1);
        __syncthreads();
    }

    const int er = lane >> 2;
    const int ec = (lane & 3) << 1;
#pragma unroll
    for (int ms = 0; ms < 4; ms++) {
        const int row = m0 + wm * 64 + ms * 16 + er;
#pragma unroll
        for (int ns = 0; ns < 8; ns++) {
            const int col = n0 + wn * 64 + ns * 8 + ec;
            *(float2*)(C + (size_t)row * HIDN + col) =
                make_float2(acc[ms][ns][0], acc[ms][ns][1]);
            *(float2*)(C + (size_t)(row + 8) * HIDN + col) =
                make_float2(acc[ms][ns][2], acc[ms][ns][3]);
        }
    }
}

// ------------------------------ rope table (double trig; fast-math-safe) ---
__global__ void __launch_bounds__(256)
rope_table()
{
    const int idx = blockIdx.x * blockDim.x + threadIdx.x;
    const int j = idx & 63;
    const int s = idx >> 6;
    const float invf = (float)pow(10000.0, -(double)(2 * j) / 128.0);
    const float ang  = (float)s * invf;
    g_cs[idx] = (float)cos((double)ang);
    g_sn[idx] = (float)sin((double)ang);
}

// ---- fused: half-split rope on Q,K + bf16 hi/lo split --------------------
__global__ void __launch_bounds__(256)
rope_split()
{
    const int idx = blockIdx.x * blockDim.x + threadIdx.x;   // < 4,194,304
    const int j = idx & 63;
    const int h = (idx >> 6) & 31;
    const int s = idx >> 11;
    const float cs = g_cs[(s << 6) + j];
    const float sn = g_sn[(s << 6) + j];
    const size_t base = (size_t)s * HIDN + h * HDIM + j;

    float q0 = g_Q[base], q1 = g_Q[base + 64];
    float a = q0 * cs - q1 * sn;
    float b = q1 * cs + q0 * sn;
    __nv_bfloat16 hh = __float2bfloat16(a);
    g_Qh[base] = hh; g_Ql[base] = __float2bfloat16(a - __bfloat162float(hh));
    hh = __float2bfloat16(b);
    g_Qh[base + 64] = hh; g_Ql[base + 64] = __float2bfloat16(b - __bfloat162float(hh));

    float k0 = g_K[base], k1 = g_K[base + 64];
    a = k0 * cs - k1 * sn;
    b = k1 * cs + k0 * sn;
    hh = __float2bfloat16(a);
    g_Kh[base] = hh; g_Kl[base] = __float2bfloat16(a - __bfloat162float(hh));
    hh = __float2bfloat16(b);
    g_Kh[base + 64] = hh; g_Kl[base + 64] = __float2bfloat16(b - __bfloat162float(hh));
}

// ---- V: per-head transpose + bf16 hi/lo split: g_Vth[h][d][s] -------------
__global__ void __launch_bounds__(256)
vt_split()
{
    const int idx = blockIdx.x * blockDim.x + threadIdx.x;   // < 8,388,608
    const int s = idx & 2047;
    const int d = (idx >> 11) & 127;
    const int h = idx >> 18;
    const float v = g_V[(size_t)s * HIDN + h * HDIM + d];
    const __nv_bfloat16 hi = __float2bfloat16(v);
    const size_t o = (size_t)h * (HDIM * S_LEN) + (size_t)d * S_LEN + s;
    g_Vth[o] = hi;
    g_Vtl[o] = __float2bfloat16(v - __bfloat162float(hi));
}

// ------------------------------ flash attention (HMMA bf16x3) ---------------
// CTA: 128 q-rows x 1 head; 8 warps x 16 rows; BN=64 keys per k-tile.
// smem element offsets (bf16):
#define FQP 136
#define FVP 72
#define OFF_QH 0
#define OFF_QL 17408
#define OFF_KH 34816
#define OFF_KL 43520
#define OFF_VH 52224
#define OFF_VL 61440
#define OFF_PH 70656
#define OFF_PL 79872
#define FLASH_SMEM_B (89088 * 2)

__global__ void __launch_bounds__(256, 1)
flash_mma()
{
    extern __shared__ __nv_bfloat16 fsm[];
    const uint32_t smb = smem_u32(fsm);
    const int tid  = threadIdx.x;
    const int lane = tid & 31;
    const int w    = tid >> 5;
    const int h    = blockIdx.y;
    const int q0   = blockIdx.x << 7;

    // load Q tile (128 x 128 bf16 hi/lo)
#pragma unroll
    for (int i = 0; i < 8; i++) {
        const int idx = tid + i * 256;          // 0..2047
        const int row = idx >> 4;
        const int col = (idx & 15) << 3;
        const size_t g = (size_t)(q0 + row) * HIDN + h * HDIM + col;
        *(uint4*)&fsm[OFF_QH + row * FQP + col] = *(const uint4*)&g_Qh[g];
        *(uint4*)&fsm[OFF_QL + row * FQP + col] = *(const uint4*)&g_Ql[g];
    }

    float o[16][4];
#pragma unroll
    for (int i = 0; i < 16; i++)
#pragma unroll
        for (int r = 0; r < 4; r++) o[i][r] = 0.f;
    float mrow[2] = {-1e30f, -1e30f};
    float lrow[2] = {0.f, 0.f};

    const int er = lane >> 2;
    const int ec = (lane & 3) << 1;
    const int nkt = (q0 >> 6) + 2;

    for (int kt = 0; kt < nkt; kt++) {
        const int k0 = kt << 6;
        __syncthreads();
        // load K (64x128) and Vt (128x64) hi/lo
#pragma unroll
        for (int i = 0; i < 4; i++) {
            const int idx = tid + i * 256;      // 0..1023
            {   // K
                const int row = idx >> 4;
                const int col = (idx & 15) << 3;
                const size_t g = (size_t)(k0 + row) * HIDN + h * HDIM + col;
                *(uint4*)&fsm[OFF_KH + row * FQP + col] = *(const uint4*)&g_Kh[g];
                *(uint4*)&fsm[OFF_KL + row * FQP + col] = *(const uint4*)&g_Kl[g];
            }
            {   // Vt
                const int d  = idx >> 3;
                const int sb = (idx & 7) << 3;
                const size_t g = (size_t)h * (HDIM * S_LEN) + (size_t)d * S_LEN + k0 + sb;
                *(uint4*)&fsm[OFF_VH + d * FVP + sb] = *(const uint4*)&g_Vth[g];
                *(uint4*)&fsm[OFF_VL + d * FVP + sb] = *(const uint4*)&g_Vtl[g];
            }
        }
        __syncthreads();

        // ---- S = Q K^T (x3 split), warp tile 16x64 ----
        float s[8][4];
#pragma unroll
        for (int i = 0; i < 8; i++)
#pragma unroll
            for (int r = 0; r < 4; r++) s[i][r] = 0.f;

        const int arow = w * 16 + (lane & 15);
        const int acol8 = (lane >> 4) << 3;
        const int brow = ((lane >> 4) << 3) + (lane & 7);
        const int bcol8 = ((lane >> 3) & 1) << 3;
#pragma unroll
        for (int ks = 0; ks < 8; ks++) {
            uint32_t ah[4], al[4];
            const uint32_t aoff = (uint32_t)(arow * FQP + ks * 16 + acol8) * 2;
            LDSM_X4(ah, smb + OFF_QH * 2 + aoff);
            LDSM_X4(al, smb + OFF_QL * 2 + aoff);
#pragma unroll
            for (int p = 0; p < 4; p++) {
                uint32_t bh[4], bl[4];
                const uint32_t boff =
                    (uint32_t)((p * 16 + brow) * FQP + ks * 16 + bcol8) * 2;
                LDSM_X4(bh, smb + OFF_KH * 2 + boff);
                LDSM_X4(bl, smb + OFF_KL * 2 + boff);
#pragma unroll
                for (int hf = 0; hf < 2; hf++) {
                    const int ns = p * 2 + hf;
                    MMA_BF16(s[ns], ah, bh[hf * 2], bh[hf * 2 + 1]);
                    MMA_BF16(s[ns], ah, bl[hf * 2], bl[hf * 2 + 1]);
                    MMA_BF16(s[ns], al, bh[hf * 2], bh[hf * 2 + 1]);
                }
            }
        }

        // ---- online softmax (fp32, frag layout) ----
        const float sc = 0.08838834764831845f;
        const bool diag = (k0 + 63 > q0);
        const uint32_t pwarp = (uint32_t)(w * 16 * FVP);
#pragma unroll
        for (int i = 0; i < 2; i++) {
            const int qg = q0 + w * 16 + er + 8 * i;
            float rmax = -1e30f;
#pragma unroll
            for (int ns = 0; ns < 8; ns++)
#pragma unroll
                for (int c = 0; c < 2; c++) {
                    float v = s[ns][i * 2 + c] * sc;
                    if (diag && (k0 + ns * 8 + ec + c > qg)) v = -1e30f;
                    s[ns][i * 2 + c] = v;
                    rmax = fmaxf(rmax, v);
                }
            rmax = fmaxf(rmax, __shfl_xor_sync(0xffffffffu, rmax, 1));
            rmax = fmaxf(rmax, __shfl_xor_sync(0xffffffffu, rmax, 2));
            const float mn = fmaxf(mrow[i], rmax);
            const float corr = __expf(mrow[i] - mn);
            mrow[i] = mn;
            float rs = 0.f;
#pragma unroll
            for (int ns = 0; ns < 8; ns++) {
                const float p0 = __expf(s[ns][i * 2 + 0] - mn);
                const float p1 = __expf(s[ns][i * 2 + 1] - mn);
                rs += p0 + p1;
                // pack hi/lo bf16 pairs
                __nv_bfloat16 h0 = __float2bfloat16(p0);
                __nv_bfloat16 h1 = __float2bfloat16(p1);
                __nv_bfloat16 l0 = __float2bfloat16(p0 - __bfloat162float(h0));
                __nv_bfloat16 l1 = __float2bfloat16(p1 - __bfloat162float(h1));
                const uint32_t hp = (uint32_t)*(unsigned short*)&h0
                                  | ((uint32_t)*(unsigned short*)&h1 << 16);
                const uint32_t lp = (uint32_t)*(unsigned short*)&l0
                                  | ((uint32_t)*(unsigned short*)&l1 << 16);
                const int pr = er + 8 * i;
                *(uint32_t*)&fsm[OFF_PH + pwarp + pr * FVP + ns * 8 + ec] = hp;
                *(uint32_t*)&fsm[OFF_PL + pwarp + pr * FVP + ns * 8 + ec] = lp;
            }
            rs += __shfl_xor_sync(0xffffffffu, rs, 1);
            rs += __shfl_xor_sync(0xffffffffu, rs, 2);
            lrow[i] = lrow[i] * corr + rs;
#pragma unroll
            for (int ns = 0; ns < 16; ns++) {
                o[ns][i * 2 + 0] *= corr;
                o[ns][i * 2 + 1] *= corr;
            }
        }
        __syncwarp();

        // ---- O += P V (x3 split): A = P (16x64), B = Vt (128x64 k-major) ----
#pragma unroll
        for (int ks = 0; ks < 4; ks++) {
            uint32_t pah[4], pal[4];
            const uint32_t aoff =
                pwarp * 2 + (uint32_t)((lane & 15) * FVP + ks * 16 + acol8) * 2;
            LDSM_X4(pah, smb + OFF_PH * 2 + aoff);
            LDSM_X4(pal, smb + OFF_PL * 2 + aoff);
#pragma unroll
            for (int p = 0; p < 8; p++) {
                uint32_t bh[4], bl[4];
                const uint32_t boff =
                    (uint32_t)((p * 16 + brow) * FVP + ks * 16 + bcol8) * 2;
                LDSM_X4(bh, smb + OFF_VH * 2 + boff);
                LDSM_X4(bl, smb + OFF_VL * 2 + boff);
#pragma unroll
                for (int hf = 0; hf < 2; hf++) {
                    const int ns = p * 2 + hf;
                    MMA_BF16(o[ns], pah, bh[hf * 2], bh[hf * 2 + 1]);
                    MMA_BF16(o[ns], pah, bl[hf * 2], bl[hf * 2 + 1]);
                    MMA_BF16(o[ns], pal, bh[hf * 2], bh[hf * 2 + 1]);
                }
            }
        }
    }

    // epilogue
    const float inv0 = 1.0f / lrow[0];
    const float inv1 = 1.0f / lrow[1];
    const int row = q0 + w * 16 + er;
#pragma unroll
    for (int ns = 0; ns < 16; ns++) {
        const int col = h * HDIM + ns * 8 + ec;
        *(float2*)(g_A + (size_t)row * HIDN + col) =
            make_float2(o[ns][0] * inv0, o[ns][1] * inv0);
        *(float2*)(g_A + (size_t)(row + 8) * HIDN + col) =
            make_float2(o[ns][2] * inv1, o[ns][3] * inv1);
    }
}

// ---------------------------------------------------------------------------
extern "C" void kernel_launch(void* const* d_in, const int* in_sizes, int n_in,
                              void* d_out, int out_size)
{
    const float* X  = (const float*)d_in[0];
    const float* Wq = (const float*)d_in[2];
    const float* Wk = (const float*)d_in[3];
    const float* Wv = (const float*)d_in[4];
    const float* Wo = (const float*)d_in[5];
    float* out = (float*)d_out;

    float *dQ, *dK, *dV, *dA;
    cudaGetSymbolAddress((void**)&dQ, g_Q);
    cudaGetSymbolAddress((void**)&dK, g_K);
    cudaGetSymbolAddress((void**)&dV, g_V);
    cudaGetSymbolAddress((void**)&dA, g_A);

    rope_table<<<(S_LEN * 64) / 256, 256>>>();

    cudaFuncSetAttribute(gemm_mma, cudaFuncAttributeMaxDynamicSharedMemorySize, GEMM_SMEM);
    const dim3 gg(HIDN / 128, S_LEN / 128);
    gemm_mma<<<gg, 128, GEMM_SMEM>>>(X, Wq, dQ);
    gemm_mma<<<gg, 128, GEMM_SMEM>>>(X, Wk, dK);
    gemm_mma<<<gg, 128, GEMM_SMEM>>>(X, Wv, dV);

    rope_split<<<(S_LEN * NHEAD * 64) / 256, 256>>>();
    vt_split<<<(NHEAD * HDIM * S_LEN) / 256, 256>>>();

    cudaFuncSetAttribute(flash_mma, cudaFuncAttributeMaxDynamicSharedMemorySize, FLASH_SMEM_B);
    flash_mma<<<dim3(S_LEN / 128, NHEAD), 256, FLASH_SMEM_B>>>();

    gemm_mma<<<gg, 128, GEMM_SMEM>>>(dA, Wo, out);
}

// round 14
// speedup vs baseline: 2.0824x; 1.1916x over previous
#include <cuda_runtime.h>
#include <cuda_fp16.h>
#include <cstdint>
#include <math.h>

#define S_LEN 2048
#define HIDN  4096
#define NHEAD 32
#define HDIM  128

// ------------------------------ scratch (static, allocation-free) ----------
__device__ float g_Q[S_LEN * HIDN];
__device__ float g_K[S_LEN * HIDN];
__device__ float g_V[S_LEN * HIDN];
__device__ float g_A[S_LEN * HIDN];
__device__ float g_cs[S_LEN * 64];
__device__ float g_sn[S_LEN * 64];

// fp16 operands for flash (Q roped+rounded; K roped+split; V transposed+split)
__device__ __half g_Qh[S_LEN * HIDN];
__device__ __half g_Kh[S_LEN * HIDN], g_Kl[S_LEN * HIDN];
__device__ __half g_Vth[NHEAD * HDIM * S_LEN], g_Vtl[NHEAD * HDIM * S_LEN];

// ------------------------------ helpers ------------------------------------
__device__ __forceinline__ uint32_t smem_u32(const void* p) {
    uint32_t a;
    asm("{ .reg .u64 t; cvta.to.shared.u64 t, %1; cvt.u32.u64 %0, t; }"
        : "=r"(a) : "l"(p));
    return a;
}

#define LDSM_X4(r, addr)                                                      \
    asm volatile("ldmatrix.sync.aligned.m8n8.x4.shared.b16 {%0,%1,%2,%3}, [%4];" \
        : "=r"((r)[0]), "=r"((r)[1]), "=r"((r)[2]), "=r"((r)[3]) : "r"(addr))

#define MMA_F16(d, a, b0, b1)                                                 \
    asm volatile("mma.sync.aligned.m16n8k16.row.col.f32.f16.f16.f32 "         \
        "{%0,%1,%2,%3}, {%4,%5,%6,%7}, {%8,%9}, {%0,%1,%2,%3};"               \
        : "+f"((d)[0]), "+f"((d)[1]), "+f"((d)[2]), "+f"((d)[3])              \
        : "r"((a)[0]), "r"((a)[1]), "r"((a)[2]), "r"((a)[3]),                 \
          "r"(b0), "r"(b1))

__device__ __forceinline__ void cvt_h4(float4 v, uint2& h)
{
    __half h0 = __float2half_rn(v.x), h1 = __float2half_rn(v.y);
    __half h2 = __float2half_rn(v.z), h3 = __float2half_rn(v.w);
    h.x = (uint32_t)*(unsigned short*)&h0 | ((uint32_t)*(unsigned short*)&h1 << 16);
    h.y = (uint32_t)*(unsigned short*)&h2 | ((uint32_t)*(unsigned short*)&h3 << 16);
}

__device__ __forceinline__ void cvt_hilo(float4 v, uint2& h, uint2& l)
{
    __half h0 = __float2half_rn(v.x), h1 = __float2half_rn(v.y);
    __half h2 = __float2half_rn(v.z), h3 = __float2half_rn(v.w);
    __half l0 = __float2half_rn(v.x - __half2float(h0));
    __half l1 = __float2half_rn(v.y - __half2float(h1));
    __half l2 = __float2half_rn(v.z - __half2float(h2));
    __half l3 = __float2half_rn(v.w - __half2float(h3));
    h.x = (uint32_t)*(unsigned short*)&h0 | ((uint32_t)*(unsigned short*)&h1 << 16);
    h.y = (uint32_t)*(unsigned short*)&h2 | ((uint32_t)*(unsigned short*)&h3 << 16);
    l.x = (uint32_t)*(unsigned short*)&l0 | ((uint32_t)*(unsigned short*)&l1 << 16);
    l.y = (uint32_t)*(unsigned short*)&l2 | ((uint32_t)*(unsigned short*)&l3 << 16);
}

// ------------------------------ HMMA fp16 2-term GEMM ----------------------
// C[m,n] = sum_k A[m,k]*B[n,k] via Ah·Bh + Ah·Bl  (A rounded, B split).
// Error: Al·B ~ 2^-12 rel, incoherent over K -> ~1.4e-4.
// CTA: 128x128, 128 thr = 4 warps (2x2), warp tile 64x64, KC=16.
#define KC    16
#define PITCH 24
#define TILE_ELEMS (128 * PITCH)
#define TILE_BYTES (TILE_ELEMS * 2)       // 6144
#define BUF_BYTES  (3 * TILE_BYTES)       // Ah, Bh, Bl = 18432
#define GEMM_SMEM  (2 * BUF_BYTES)        // 36864

__global__ void __launch_bounds__(128, 2)
gemm_mma(const float* __restrict__ A, const float* __restrict__ B,
         float* __restrict__ C)
{
    extern __shared__ char smraw[];
    __half* sh = (__half*)smraw;
    const uint32_t smb = smem_u32(sh);

    const int tid  = threadIdx.x;
    const int lane = tid & 31;
    const int wid  = tid >> 5;
    const int wm   = wid & 1;
    const int wn   = wid >> 1;
    const int m0   = blockIdx.y << 7;
    const int n0   = blockIdx.x << 7;

    float acc[4][8][4];
#pragma unroll
    for (int i = 0; i < 4; i++)
#pragma unroll
        for (int j = 0; j < 8; j++)
#pragma unroll
            for (int r = 0; r < 4; r++) acc[i][j][r] = 0.f;

    float4 reg[8];

    auto ldg_chunk = [&](int k0) {
#pragma unroll
        for (int i = 0; i < 4; i++) {
            const int idx = tid + i * 128;
            const int row = idx >> 2;
            const int col = (idx & 3) << 2;
            reg[i]     = *(const float4*)(A + (size_t)(m0 + row) * HIDN + k0 + col);
            reg[4 + i] = *(const float4*)(B + (size_t)(n0 + row) * HIDN + k0 + col);
        }
    };
    auto sts_chunk = [&](int b) {
        __half* Ah = sh + b * 3 * TILE_ELEMS;
        __half* Bh = Ah + TILE_ELEMS;
        __half* Bl = Ah + 2 * TILE_ELEMS;
#pragma unroll
        for (int i = 0; i < 4; i++) {
            const int idx = tid + i * 128;
            const int row = idx >> 2;
            const int col = (idx & 3) << 2;
            uint2 h, l;
            cvt_h4(reg[i], h);
            *(uint2*)&Ah[row * PITCH + col] = h;
            cvt_hilo(reg[4 + i], h, l);
            *(uint2*)&Bh[row * PITCH + col] = h;
            *(uint2*)&Bl[row * PITCH + col] = l;
        }
    };

    auto compute = [&](int b) {
        const uint32_t base = smb + b * BUF_BYTES;
        const uint32_t Ah = base;
        const uint32_t Bh = base + TILE_BYTES;
        const uint32_t Bl = base + 2 * TILE_BYTES;

        const int arow = wm * 64 + (lane & 15);
        const int acol = (lane >> 4) << 3;
        const int brow = wn * 64 + ((lane >> 4) << 3) + (lane & 7);
        const int bcol = ((lane >> 3) & 1) << 3;

        uint32_t ah[4][4];
#pragma unroll
        for (int ms = 0; ms < 4; ms++) {
            const uint32_t off = ((arow + ms * 16) * PITCH + acol) * 2;
            LDSM_X4(ah[ms], Ah + off);
        }
#pragma unroll
        for (int p = 0; p < 4; p++) {
            uint32_t bh[4], bl[4];
            const uint32_t off = ((brow + p * 16) * PITCH + bcol) * 2;
            LDSM_X4(bh, Bh + off);
            LDSM_X4(bl, Bl + off);
#pragma unroll
            for (int ms = 0; ms < 4; ms++)
#pragma unroll
                for (int hf = 0; hf < 2; hf++) {
                    const int ns = p * 2 + hf;
                    MMA_F16(acc[ms][ns], ah[ms], bh[hf * 2], bh[hf * 2 + 1]);
                    MMA_F16(acc[ms][ns], ah[ms], bl[hf * 2], bl[hf * 2 + 1]);
                }
        }
    };

    ldg_chunk(0);
    sts_chunk(0);
    __syncthreads();

    const int NCHUNK = HIDN / KC;
    for (int c = 0; c < NCHUNK; c++) {
        if (c + 1 < NCHUNK) ldg_chunk((c + 1) * KC);
        compute(c & 1);
        if (c + 1 < NCHUNK) sts_chunk((c + 1) & 1);
        __syncthreads();
    }

    const int er = lane >> 2;
    const int ec = (lane & 3) << 1;
#pragma unroll
    for (int ms = 0; ms < 4; ms++) {
        const int row = m0 + wm * 64 + ms * 16 + er;
#pragma unroll
        for (int ns = 0; ns < 8; ns++) {
            const int col = n0 + wn * 64 + ns * 8 + ec;
            *(float2*)(C + (size_t)row * HIDN + col) =
                make_float2(acc[ms][ns][0], acc[ms][ns][1]);
            *(float2*)(C + (size_t)(row + 8) * HIDN + col) =
                make_float2(acc[ms][ns][2], acc[ms][ns][3]);
        }
    }
}

// ------------------------------ rope table (double trig; fast-math-safe) ---
__global__ void __launch_bounds__(256)
rope_table()
{
    const int idx = blockIdx.x * blockDim.x + threadIdx.x;
    const int j = idx & 63;
    const int s = idx >> 6;
    const float invf = (float)pow(10000.0, -(double)(2 * j) / 128.0);
    const float ang  = (float)s * invf;
    g_cs[idx] = (float)cos((double)ang);
    g_sn[idx] = (float)sin((double)ang);
}

// ---- fused: half-split rope on Q,K; Q rounded to fp16, K split hi/lo ------
__global__ void __launch_bounds__(256)
rope_split()
{
    const int idx = blockIdx.x * blockDim.x + threadIdx.x;   // < 4,194,304
    const int j = idx & 63;
    const int h = (idx >> 6) & 31;
    const int s = idx >> 11;
    const float cs = g_cs[(s << 6) + j];
    const float sn = g_sn[(s << 6) + j];
    const size_t base = (size_t)s * HIDN + h * HDIM + j;

    const float q0 = g_Q[base], q1 = g_Q[base + 64];
    g_Qh[base]      = __float2half_rn(q0 * cs - q1 * sn);
    g_Qh[base + 64] = __float2half_rn(q1 * cs + q0 * sn);

    const float k0 = g_K[base], k1 = g_K[base + 64];
    float a = k0 * cs - k1 * sn;
    float b = k1 * cs + k0 * sn;
    __half hh = __float2half_rn(a);
    g_Kh[base] = hh; g_Kl[base] = __float2half_rn(a - __half2float(hh));
    hh = __float2half_rn(b);
    g_Kh[base + 64] = hh; g_Kl[base + 64] = __float2half_rn(b - __half2float(hh));
}

// ---- V: per-head transpose + fp16 hi/lo split: g_Vth[h][d][s] -------------
__global__ void __launch_bounds__(256)
vt_split()
{
    const int idx = blockIdx.x * blockDim.x + threadIdx.x;   // < 8,388,608
    const int s = idx & 2047;
    const int d = (idx >> 11) & 127;
    const int h = idx >> 18;
    const float v = g_V[(size_t)s * HIDN + h * HDIM + d];
    const __half hi = __float2half_rn(v);
    const size_t o = (size_t)h * (HDIM * S_LEN) + (size_t)d * S_LEN + s;
    g_Vth[o] = hi;
    g_Vtl[o] = __float2half_rn(v - __half2float(hi));
}

// ------------------------------ flash attention (HMMA fp16 2-term) ---------
// CTA: 128 q-rows x 1 head; 8 warps x 16 rows; BN=64 keys per k-tile.
// S = Qh·(Kh+Kl); O += Ph·(Vh+Vl).  smem element offsets (fp16):
#define FQP 136
#define FVP 72
#define OFF_QH 0
#define OFF_KH 17408
#define OFF_KL 26112
#define OFF_VH 34816
#define OFF_VL 44032
#define OFF_PH 53248
#define FLASH_SMEM_B (62464 * 2)

__global__ void __launch_bounds__(256, 1)
flash_mma()
{
    extern __shared__ __half fsm[];
    const uint32_t smb = smem_u32(fsm);
    const int tid  = threadIdx.x;
    const int lane = tid & 31;
    const int w    = tid >> 5;
    const int h    = blockIdx.y;
    const int q0   = blockIdx.x << 7;

    // load Q tile (128 x 128 fp16, rounded)
#pragma unroll
    for (int i = 0; i < 8; i++) {
        const int idx = tid + i * 256;          // 0..2047
        const int row = idx >> 4;
        const int col = (idx & 15) << 3;
        const size_t g = (size_t)(q0 + row) * HIDN + h * HDIM + col;
        *(uint4*)&fsm[OFF_QH + row * FQP + col] = *(const uint4*)&g_Qh[g];
    }

    float o[16][4];
#pragma unroll
    for (int i = 0; i < 16; i++)
#pragma unroll
        for (int r = 0; r < 4; r++) o[i][r] = 0.f;
    float mrow[2] = {-1e30f, -1e30f};
    float lrow[2] = {0.f, 0.f};

    const int er = lane >> 2;
    const int ec = (lane & 3) << 1;
    const int nkt = (q0 >> 6) + 2;

    for (int kt = 0; kt < nkt; kt++) {
        const int k0 = kt << 6;
        __syncthreads();
#pragma unroll
        for (int i = 0; i < 4; i++) {
            const int idx = tid + i * 256;      // 0..1023
            {   // K hi/lo (64 x 128)
                const int row = idx >> 4;
                const int col = (idx & 15) << 3;
                const size_t g = (size_t)(k0 + row) * HIDN + h * HDIM + col;
                *(uint4*)&fsm[OFF_KH + row * FQP + col] = *(const uint4*)&g_Kh[g];
                *(uint4*)&fsm[OFF_KL + row * FQP + col] = *(const uint4*)&g_Kl[g];
            }
            {   // Vt hi/lo (128 x 64)
                const int d  = idx >> 3;
                const int sb = (idx & 7) << 3;
                const size_t g = (size_t)h * (HDIM * S_LEN) + (size_t)d * S_LEN + k0 + sb;
                *(uint4*)&fsm[OFF_VH + d * FVP + sb] = *(const uint4*)&g_Vth[g];
                *(uint4*)&fsm[OFF_VL + d * FVP + sb] = *(const uint4*)&g_Vtl[g];
            }
        }
        __syncthreads();

        // ---- S = Q K^T (2-term), warp tile 16x64 ----
        float s[8][4];
#pragma unroll
        for (int i = 0; i < 8; i++)
#pragma unroll
            for (int r = 0; r < 4; r++) s[i][r] = 0.f;

        const int arow = w * 16 + (lane & 15);
        const int acol8 = (lane >> 4) << 3;
        const int brow = ((lane >> 4) << 3) + (lane & 7);
        const int bcol8 = ((lane >> 3) & 1) << 3;
#pragma unroll
        for (int ks = 0; ks < 8; ks++) {
            uint32_t ah[4];
            const uint32_t aoff = (uint32_t)(arow * FQP + ks * 16 + acol8) * 2;
            LDSM_X4(ah, smb + OFF_QH * 2 + aoff);
#pragma unroll
            for (int p = 0; p < 4; p++) {
                uint32_t bh[4], bl[4];
                const uint32_t boff =
                    (uint32_t)((p * 16 + brow) * FQP + ks * 16 + bcol8) * 2;
                LDSM_X4(bh, smb + OFF_KH * 2 + boff);
                LDSM_X4(bl, smb + OFF_KL * 2 + boff);
#pragma unroll
                for (int hf = 0; hf < 2; hf++) {
                    const int ns = p * 2 + hf;
                    MMA_F16(s[ns], ah, bh[hf * 2], bh[hf * 2 + 1]);
                    MMA_F16(s[ns], ah, bl[hf * 2], bl[hf * 2 + 1]);
                }
            }
        }

        // ---- online softmax (fp32, frag layout) ----
        const float sc = 0.08838834764831845f;
        const bool diag = (k0 + 63 > q0);
        const uint32_t pwarp = (uint32_t)(w * 16 * FVP);
#pragma unroll
        for (int i = 0; i < 2; i++) {
            const int qg = q0 + w * 16 + er + 8 * i;
            float rmax = -1e30f;
#pragma unroll
            for (int ns = 0; ns < 8; ns++)
#pragma unroll
                for (int c = 0; c < 2; c++) {
                    float v = s[ns][i * 2 + c] * sc;
                    if (diag && (k0 + ns * 8 + ec + c > qg)) v = -1e30f;
                    s[ns][i * 2 + c] = v;
                    rmax = fmaxf(rmax, v);
                }
            rmax = fmaxf(rmax, __shfl_xor_sync(0xffffffffu, rmax, 1));
            rmax = fmaxf(rmax, __shfl_xor_sync(0xffffffffu, rmax, 2));
            const float mn = fmaxf(mrow[i], rmax);
            const float corr = __expf(mrow[i] - mn);
            mrow[i] = mn;
            float rs = 0.f;
#pragma unroll
            for (int ns = 0; ns < 8; ns++) {
                const float p0 = __expf(s[ns][i * 2 + 0] - mn);
                const float p1 = __expf(s[ns][i * 2 + 1] - mn);
                rs += p0 + p1;
                __half h0 = __float2half_rn(p0);
                __half h1 = __float2half_rn(p1);
                const uint32_t hp = (uint32_t)*(unsigned short*)&h0
                                  | ((uint32_t)*(unsigned short*)&h1 << 16);
                const int pr = er + 8 * i;
                *(uint32_t*)&fsm[OFF_PH + pwarp + pr * FVP + ns * 8 + ec] = hp;
            }
            rs += __shfl_xor_sync(0xffffffffu, rs, 1);
            rs += __shfl_xor_sync(0xffffffffu, rs, 2);
            lrow[i] = lrow[i] * corr + rs;
#pragma unroll
            for (int ns = 0; ns < 16; ns++) {
                o[ns][i * 2 + 0] *= corr;
                o[ns][i * 2 + 1] *= corr;
            }
        }
        __syncwarp();

        // ---- O += P V (2-term): A = P (16x64), B = Vt (128x64 k-major) ----
#pragma unroll
        for (int ks = 0; ks < 4; ks++) {
            uint32_t pah[4];
            const uint32_t aoff =
                pwarp * 2 + (uint32_t)((lane & 15) * FVP + ks * 16 + acol8) * 2;
            LDSM_X4(pah, smb + OFF_PH * 2 + aoff);
#pragma unroll
            for (int p = 0; p < 8; p++) {
                uint32_t bh[4], bl[4];
                const uint32_t boff =
                    (uint32_t)((p * 16 + brow) * FVP + ks * 16 + bcol8) * 2;
                LDSM_X4(bh, smb + OFF_VH * 2 + boff);
                LDSM_X4(bl, smb + OFF_VL * 2 + boff);
#pragma unroll
                for (int hf = 0; hf < 2; hf++) {
                    const int ns = p * 2 + hf;
                    MMA_F16(o[ns], pah, bh[hf * 2], bh[hf * 2 + 1]);
                    MMA_F16(o[ns], pah, bl[hf * 2], bl[hf * 2 + 1]);
                }
            }
        }
    }

    // epilogue
    const float inv0 = 1.0f / lrow[0];
    const float inv1 = 1.0f / lrow[1];
    const int row = q0 + w * 16 + er;
#pragma unroll
    for (int ns = 0; ns < 16; ns++) {
        const int col = h * HDIM + ns * 8 + ec;
        *(float2*)(g_A + (size_t)row * HIDN + col) =
            make_float2(o[ns][0] * inv0, o[ns][1] * inv0);
        *(float2*)(g_A + (size_t)(row + 8) * HIDN + col) =
            make_float2(o[ns][2] * inv1, o[ns][3] * inv1);
    }
}

// ---------------------------------------------------------------------------
extern "C" void kernel_launch(void* const* d_in, const int* in_sizes, int n_in,
                              void* d_out, int out_size)
{
    const float* X  = (const float*)d_in[0];
    const float* Wq = (const float*)d_in[2];
    const float* Wk = (const float*)d_in[3];
    const float* Wv = (const float*)d_in[4];
    const float* Wo = (const float*)d_in[5];
    float* out = (float*)d_out;

    float *dQ, *dK, *dV, *dA;
    cudaGetSymbolAddress((void**)&dQ, g_Q);
    cudaGetSymbolAddress((void**)&dK, g_K);
    cudaGetSymbolAddress((void**)&dV, g_V);
    cudaGetSymbolAddress((void**)&dA, g_A);

    rope_table<<<(S_LEN * 64) / 256, 256>>>();

    cudaFuncSetAttribute(gemm_mma, cudaFuncAttributeMaxDynamicSharedMemorySize, GEMM_SMEM);
    const dim3 gg(HIDN / 128, S_LEN / 128);
    gemm_mma<<<gg, 128, GEMM_SMEM>>>(X, Wq, dQ);
    gemm_mma<<<gg, 128, GEMM_SMEM>>>(X, Wk, dK);
    gemm_mma<<<gg, 128, GEMM_SMEM>>>(X, Wv, dV);

    rope_split<<<(S_LEN * NHEAD * 64) / 256, 256>>>();
    vt_split<<<(NHEAD * HDIM * S_LEN) / 256, 256>>>();

    cudaFuncSetAttribute(flash_mma, cudaFuncAttributeMaxDynamicSharedMemorySize, FLASH_SMEM_B);
    flash_mma<<<dim3(S_LEN / 128, NHEAD), 256, FLASH_SMEM_B>>>();

    gemm_mma<<<gg, 128, GEMM_SMEM>>>(dA, Wo, out);
}

// round 15
// speedup vs baseline: 2.2987x; 1.1039x over previous
#include <cuda_runtime.h>
#include <cuda_fp16.h>
#include <cstdint>
#include <math.h>

#define S_LEN 2048
#define HIDN  4096
#define NHEAD 32
#define HDIM  128

// ------------------------------ scratch (static, allocation-free) ----------
__device__ float g_Q[S_LEN * HIDN];
__device__ float g_K[S_LEN * HIDN];
__device__ float g_V[S_LEN * HIDN];
__device__ float g_cs[S_LEN * 64];
__device__ float g_sn[S_LEN * 64];

// fp16 operands (pre-split, hot loops are conversion-free)
__device__ __half g_Xh[S_LEN * HIDN];                       // X rounded (A-side)
__device__ __half g_Ah[S_LEN * HIDN];                       // attn out rounded
__device__ __half g_Wqh[HIDN * HIDN], g_Wql[HIDN * HIDN];
__device__ __half g_Wkh[HIDN * HIDN], g_Wkl[HIDN * HIDN];
__device__ __half g_Wvh[HIDN * HIDN], g_Wvl[HIDN * HIDN];
__device__ __half g_Woh[HIDN * HIDN], g_Wol[HIDN * HIDN];
__device__ __half g_Qh[S_LEN * HIDN];
__device__ __half g_Kh[S_LEN * HIDN], g_Kl[S_LEN * HIDN];
__device__ __half g_Vth[NHEAD * HDIM * S_LEN], g_Vtl[NHEAD * HDIM * S_LEN];

// ------------------------------ helpers ------------------------------------
__device__ __forceinline__ uint32_t smem_u32(const void* p) {
    uint32_t a;
    asm("{ .reg .u64 t; cvta.to.shared.u64 t, %1; cvt.u32.u64 %0, t; }"
        : "=r"(a) : "l"(p));
    return a;
}

#define LDSM_X4(r, addr)                                                      \
    asm volatile("ldmatrix.sync.aligned.m8n8.x4.shared.b16 {%0,%1,%2,%3}, [%4];" \
        : "=r"((r)[0]), "=r"((r)[1]), "=r"((r)[2]), "=r"((r)[3]) : "r"(addr))

#define MMA_F16(d, a, b0, b1)                                                 \
    asm volatile("mma.sync.aligned.m16n8k16.row.col.f32.f16.f16.f32 "         \
        "{%0,%1,%2,%3}, {%4,%5,%6,%7}, {%8,%9}, {%0,%1,%2,%3};"               \
        : "+f"((d)[0]), "+f"((d)[1]), "+f"((d)[2]), "+f"((d)[3])              \
        : "r"((a)[0]), "r"((a)[1]), "r"((a)[2]), "r"((a)[3]),                 \
          "r"(b0), "r"(b1))

#define CP_ASYNC16(sm, gp)                                                    \
    asm volatile("cp.async.cg.shared.global [%0], [%1], 16;"                  \
                 :: "r"(sm), "l"(gp))
#define CP_COMMIT() asm volatile("cp.async.commit_group;" ::: "memory")
#define CP_WAIT0()  asm volatile("cp.async.wait_group 0;" ::: "memory")

__device__ __forceinline__ void cvt_h4(float4 v, uint2& h)
{
    __half h0 = __float2half_rn(v.x), h1 = __float2half_rn(v.y);
    __half h2 = __float2half_rn(v.z), h3 = __float2half_rn(v.w);
    h.x = (uint32_t)*(unsigned short*)&h0 | ((uint32_t)*(unsigned short*)&h1 << 16);
    h.y = (uint32_t)*(unsigned short*)&h2 | ((uint32_t)*(unsigned short*)&h3 << 16);
}

__device__ __forceinline__ void cvt_hilo(float4 v, uint2& h, uint2& l)
{
    __half h0 = __float2half_rn(v.x), h1 = __float2half_rn(v.y);
    __half h2 = __float2half_rn(v.z), h3 = __float2half_rn(v.w);
    __half l0 = __float2half_rn(v.x - __half2float(h0));
    __half l1 = __float2half_rn(v.y - __half2float(h1));
    __half l2 = __float2half_rn(v.z - __half2float(h2));
    __half l3 = __float2half_rn(v.w - __half2float(h3));
    h.x = (uint32_t)*(unsigned short*)&h0 | ((uint32_t)*(unsigned short*)&h1 << 16);
    h.y = (uint32_t)*(unsigned short*)&h2 | ((uint32_t)*(unsigned short*)&h3 << 16);
    l.x = (uint32_t)*(unsigned short*)&l0 | ((uint32_t)*(unsigned short*)&l1 << 16);
    l.y = (uint32_t)*(unsigned short*)&l2 | ((uint32_t)*(unsigned short*)&l3 << 16);
}

// ------------------------------ split kernels -------------------------------
__global__ void __launch_bounds__(256)
split_round(const float* __restrict__ src, __half* __restrict__ dst)
{
    const int i = blockIdx.x * blockDim.x + threadIdx.x;
    const float4 v = *(const float4*)(src + 4 * (size_t)i);
    uint2 h;
    cvt_h4(v, h);
    *(uint2*)(dst + 4 * (size_t)i) = h;
}

__global__ void __launch_bounds__(256)
split_hilo(const float* __restrict__ src, __half* __restrict__ hi,
           __half* __restrict__ lo)
{
    const int i = blockIdx.x * blockDim.x + threadIdx.x;
    const float4 v = *(const float4*)(src + 4 * (size_t)i);
    uint2 h, l;
    cvt_hilo(v, h, l);
    *(uint2*)(hi + 4 * (size_t)i) = h;
    *(uint2*)(lo + 4 * (size_t)i) = l;
}

// ------------------------------ HMMA fp16 2-term GEMM (cp.async loader) ----
// C[m,n] = sum_k A[m,k]*B[n,k] via Ah·Bh + Ah·Bl, all operands pre-split fp16.
// CTA: 128x128, 128 thr = 4 warps (2x2), warp tile 64x64, KC=16, 2-stage pipe.
#define KC    16
#define PITCH 24
#define TILE_ELEMS (128 * PITCH)
#define TILE_BYTES (TILE_ELEMS * 2)       // 6144
#define BUF_BYTES  (3 * TILE_BYTES)       // Ah, Bh, Bl = 18432
#define GEMM_SMEM  (2 * BUF_BYTES)        // 36864

__global__ void __launch_bounds__(128, 2)
gemm_f16(const __half* __restrict__ Ag, const __half* __restrict__ Bhg,
         const __half* __restrict__ Blg, float* __restrict__ C)
{
    extern __shared__ char smraw[];
    const uint32_t smb = smem_u32(smraw);

    const int tid  = threadIdx.x;
    const int lane = tid & 31;
    const int wid  = tid >> 5;
    const int wm   = wid & 1;
    const int wn   = wid >> 1;
    const int m0   = blockIdx.y << 7;
    const int n0   = blockIdx.x << 7;

    float acc[4][8][4];
#pragma unroll
    for (int i = 0; i < 4; i++)
#pragma unroll
        for (int j = 0; j < 8; j++)
#pragma unroll
            for (int r = 0; r < 4; r++) acc[i][j][r] = 0.f;

    // cp.async loader: 768 x 16B per chunk (3 tiles x 128 rows x 2 halves)
    auto load_chunk = [&](int k0, int b) {
        const uint32_t base = smb + b * BUF_BYTES;
#pragma unroll
        for (int i = 0; i < 6; i++) {
            const int idx  = tid + i * 128;        // 0..767
            const int tile = idx >> 8;
            const int q    = idx & 255;
            const int r    = q >> 1;
            const int half = q & 1;
            const __half* gp =
                (tile == 0) ? Ag  + (size_t)(m0 + r) * HIDN + k0 + half * 8 :
                (tile == 1) ? Bhg + (size_t)(n0 + r) * HIDN + k0 + half * 8 :
                              Blg + (size_t)(n0 + r) * HIDN + k0 + half * 8;
            const uint32_t sm = base + tile * TILE_BYTES + (r * PITCH + half * 8) * 2;
            CP_ASYNC16(sm, gp);
        }
    };

    auto compute = [&](int b) {
        const uint32_t base = smb + b * BUF_BYTES;
        const uint32_t Ah = base;
        const uint32_t Bh = base + TILE_BYTES;
        const uint32_t Bl = base + 2 * TILE_BYTES;

        const int arow = wm * 64 + (lane & 15);
        const int acol = (lane >> 4) << 3;
        const int brow = wn * 64 + ((lane >> 4) << 3) + (lane & 7);
        const int bcol = ((lane >> 3) & 1) << 3;

        uint32_t ah[4][4];
#pragma unroll
        for (int ms = 0; ms < 4; ms++) {
            const uint32_t off = ((arow + ms * 16) * PITCH + acol) * 2;
            LDSM_X4(ah[ms], Ah + off);
        }
#pragma unroll
        for (int p = 0; p < 4; p++) {
            uint32_t bh[4], bl[4];
            const uint32_t off = ((brow + p * 16) * PITCH + bcol) * 2;
            LDSM_X4(bh, Bh + off);
            LDSM_X4(bl, Bl + off);
#pragma unroll
            for (int ms = 0; ms < 4; ms++)
#pragma unroll
                for (int hf = 0; hf < 2; hf++) {
                    const int ns = p * 2 + hf;
                    MMA_F16(acc[ms][ns], ah[ms], bh[hf * 2], bh[hf * 2 + 1]);
                    MMA_F16(acc[ms][ns], ah[ms], bl[hf * 2], bl[hf * 2 + 1]);
                }
        }
    };

    load_chunk(0, 0);
    CP_COMMIT();

    const int NCHUNK = HIDN / KC;   // 256
    for (int c = 0; c < NCHUNK; c++) {
        CP_WAIT0();
        __syncthreads();            // chunk c visible to all; prev compute done
        if (c + 1 < NCHUNK) {
            load_chunk((c + 1) * KC, (c + 1) & 1);
            CP_COMMIT();
        }
        compute(c & 1);
    }

    const int er = lane >> 2;
    const int ec = (lane & 3) << 1;
#pragma unroll
    for (int ms = 0; ms < 4; ms++) {
        const int row = m0 + wm * 64 + ms * 16 + er;
#pragma unroll
        for (int ns = 0; ns < 8; ns++) {
            const int col = n0 + wn * 64 + ns * 8 + ec;
            *(float2*)(C + (size_t)row * HIDN + col) =
                make_float2(acc[ms][ns][0], acc[ms][ns][1]);
            *(float2*)(C + (size_t)(row + 8) * HIDN + col) =
                make_float2(acc[ms][ns][2], acc[ms][ns][3]);
        }
    }
}

// ------------------------------ rope table (double trig; fast-math-safe) ---
__global__ void __launch_bounds__(256)
rope_table()
{
    const int idx = blockIdx.x * blockDim.x + threadIdx.x;
    const int j = idx & 63;
    const int s = idx >> 6;
    const float invf = (float)pow(10000.0, -(double)(2 * j) / 128.0);
    const float ang  = (float)s * invf;
    g_cs[idx] = (float)cos((double)ang);
    g_sn[idx] = (float)sin((double)ang);
}

// ---- fused: half-split rope on Q,K; Q rounded to fp16, K split hi/lo ------
__global__ void __launch_bounds__(256)
rope_split()
{
    const int idx = blockIdx.x * blockDim.x + threadIdx.x;   // < 4,194,304
    const int j = idx & 63;
    const int h = (idx >> 6) & 31;
    const int s = idx >> 11;
    const float cs = g_cs[(s << 6) + j];
    const float sn = g_sn[(s << 6) + j];
    const size_t base = (size_t)s * HIDN + h * HDIM + j;

    const float q0 = g_Q[base], q1 = g_Q[base + 64];
    g_Qh[base]      = __float2half_rn(q0 * cs - q1 * sn);
    g_Qh[base + 64] = __float2half_rn(q1 * cs + q0 * sn);

    const float k0 = g_K[base], k1 = g_K[base + 64];
    float a = k0 * cs - k1 * sn;
    float b = k1 * cs + k0 * sn;
    __half hh = __float2half_rn(a);
    g_Kh[base] = hh; g_Kl[base] = __float2half_rn(a - __half2float(hh));
    hh = __float2half_rn(b);
    g_Kh[base + 64] = hh; g_Kl[base + 64] = __float2half_rn(b - __half2float(hh));
}

// ---- V: per-head transpose + fp16 hi/lo split: g_Vth[h][d][s] -------------
__global__ void __launch_bounds__(256)
vt_split()
{
    const int idx = blockIdx.x * blockDim.x + threadIdx.x;   // < 8,388,608
    const int s = idx & 2047;
    const int d = (idx >> 11) & 127;
    const int h = idx >> 18;
    const float v = g_V[(size_t)s * HIDN + h * HDIM + d];
    const __half hi = __float2half_rn(v);
    const size_t o = (size_t)h * (HDIM * S_LEN) + (size_t)d * S_LEN + s;
    g_Vth[o] = hi;
    g_Vtl[o] = __float2half_rn(v - __half2float(hi));
}

// ------------------------------ flash attention (HMMA fp16 2-term) ---------
#define FQP 136
#define FVP 72
#define OFF_QH 0
#define OFF_KH 17408
#define OFF_KL 26112
#define OFF_VH 34816
#define OFF_VL 44032
#define OFF_PH 53248
#define FLASH_SMEM_B (62464 * 2)

__global__ void __launch_bounds__(256, 1)
flash_mma()
{
    extern __shared__ __half fsm[];
    const uint32_t smb = smem_u32(fsm);
    const int tid  = threadIdx.x;
    const int lane = tid & 31;
    const int w    = tid >> 5;
    const int h    = blockIdx.y;
    const int q0   = blockIdx.x << 7;

#pragma unroll
    for (int i = 0; i < 8; i++) {
        const int idx = tid + i * 256;
        const int row = idx >> 4;
        const int col = (idx & 15) << 3;
        const size_t g = (size_t)(q0 + row) * HIDN + h * HDIM + col;
        *(uint4*)&fsm[OFF_QH + row * FQP + col] = *(const uint4*)&g_Qh[g];
    }

    float o[16][4];
#pragma unroll
    for (int i = 0; i < 16; i++)
#pragma unroll
        for (int r = 0; r < 4; r++) o[i][r] = 0.f;
    float mrow[2] = {-1e30f, -1e30f};
    float lrow[2] = {0.f, 0.f};

    const int er = lane >> 2;
    const int ec = (lane & 3) << 1;
    const int nkt = (q0 >> 6) + 2;

    for (int kt = 0; kt < nkt; kt++) {
        const int k0 = kt << 6;
        __syncthreads();
#pragma unroll
        for (int i = 0; i < 4; i++) {
            const int idx = tid + i * 256;
            {
                const int row = idx >> 4;
                const int col = (idx & 15) << 3;
                const size_t g = (size_t)(k0 + row) * HIDN + h * HDIM + col;
                *(uint4*)&fsm[OFF_KH + row * FQP + col] = *(const uint4*)&g_Kh[g];
                *(uint4*)&fsm[OFF_KL + row * FQP + col] = *(const uint4*)&g_Kl[g];
            }
            {
                const int d  = idx >> 3;
                const int sb = (idx & 7) << 3;
                const size_t g = (size_t)h * (HDIM * S_LEN) + (size_t)d * S_LEN + k0 + sb;
                *(uint4*)&fsm[OFF_VH + d * FVP + sb] = *(const uint4*)&g_Vth[g];
                *(uint4*)&fsm[OFF_VL + d * FVP + sb] = *(const uint4*)&g_Vtl[g];
            }
        }
        __syncthreads();

        float s[8][4];
#pragma unroll
        for (int i = 0; i < 8; i++)
#pragma unroll
            for (int r = 0; r < 4; r++) s[i][r] = 0.f;

        const int arow = w * 16 + (lane & 15);
        const int acol8 = (lane >> 4) << 3;
        const int brow = ((lane >> 4) << 3) + (lane & 7);
        const int bcol8 = ((lane >> 3) & 1) << 3;
#pragma unroll
        for (int ks = 0; ks < 8; ks++) {
            uint32_t ah[4];
            const uint32_t aoff = (uint32_t)(arow * FQP + ks * 16 + acol8) * 2;
            LDSM_X4(ah, smb + OFF_QH * 2 + aoff);
#pragma unroll
            for (int p = 0; p < 4; p++) {
                uint32_t bh[4], bl[4];
                const uint32_t boff =
                    (uint32_t)((p * 16 + brow) * FQP + ks * 16 + bcol8) * 2;
                LDSM_X4(bh, smb + OFF_KH * 2 + boff);
                LDSM_X4(bl, smb + OFF_KL * 2 + boff);
#pragma unroll
                for (int hf = 0; hf < 2; hf++) {
                    const int ns = p * 2 + hf;
                    MMA_F16(s[ns], ah, bh[hf * 2], bh[hf * 2 + 1]);
                    MMA_F16(s[ns], ah, bl[hf * 2], bl[hf * 2 + 1]);
                }
            }
        }

        const float sc = 0.08838834764831845f;
        const bool diag = (k0 + 63 > q0);
        const uint32_t pwarp = (uint32_t)(w * 16 * FVP);
#pragma unroll
        for (int i = 0; i < 2; i++) {
            const int qg = q0 + w * 16 + er + 8 * i;
            float rmax = -1e30f;
#pragma unroll
            for (int ns = 0; ns < 8; ns++)
#pragma unroll
                for (int c = 0; c < 2; c++) {
                    float v = s[ns][i * 2 + c] * sc;
                    if (diag && (k0 + ns * 8 + ec + c > qg)) v = -1e30f;
                    s[ns][i * 2 + c] = v;
                    rmax = fmaxf(rmax, v);
                }
            rmax = fmaxf(rmax, __shfl_xor_sync(0xffffffffu, rmax, 1));
            rmax = fmaxf(rmax, __shfl_xor_sync(0xffffffffu, rmax, 2));
            const float mn = fmaxf(mrow[i], rmax);
            const float corr = __expf(mrow[i] - mn);
            mrow[i] = mn;
            float rs = 0.f;
#pragma unroll
            for (int ns = 0; ns < 8; ns++) {
                const float p0 = __expf(s[ns][i * 2 + 0] - mn);
                const float p1 = __expf(s[ns][i * 2 + 1] - mn);
                rs += p0 + p1;
                __half h0 = __float2half_rn(p0);
                __half h1 = __float2half_rn(p1);
                const uint32_t hp = (uint32_t)*(unsigned short*)&h0
                                  | ((uint32_t)*(unsigned short*)&h1 << 16);
                const int pr = er + 8 * i;
                *(uint32_t*)&fsm[OFF_PH + pwarp + pr * FVP + ns * 8 + ec] = hp;
            }
            rs += __shfl_xor_sync(0xffffffffu, rs, 1);
            rs += __shfl_xor_sync(0xffffffffu, rs, 2);
            lrow[i] = lrow[i] * corr + rs;
#pragma unroll
            for (int ns = 0; ns < 16; ns++) {
                o[ns][i * 2 + 0] *= corr;
                o[ns][i * 2 + 1] *= corr;
            }
        }
        __syncwarp();

#pragma unroll
        for (int ks = 0; ks < 4; ks++) {
            uint32_t pah[4];
            const uint32_t aoff =
                pwarp * 2 + (uint32_t)((lane & 15) * FVP + ks * 16 + acol8) * 2;
            LDSM_X4(pah, smb + OFF_PH * 2 + aoff);
#pragma unroll
            for (int p = 0; p < 8; p++) {
                uint32_t bh[4], bl[4];
                const uint32_t boff =
                    (uint32_t)((p * 16 + brow) * FVP + ks * 16 + bcol8) * 2;
                LDSM_X4(bh, smb + OFF_VH * 2 + boff);
                LDSM_X4(bl, smb + OFF_VL * 2 + boff);
#pragma unroll
                for (int hf = 0; hf < 2; hf++) {
                    const int ns = p * 2 + hf;
                    MMA_F16(o[ns], pah, bh[hf * 2], bh[hf * 2 + 1]);
                    MMA_F16(o[ns], pah, bl[hf * 2], bl[hf * 2 + 1]);
                }
            }
        }
    }

    // epilogue: write attention output directly as fp16 (A-side of final GEMM)
    const float inv0 = 1.0f / lrow[0];
    const float inv1 = 1.0f / lrow[1];
    const int row = q0 + w * 16 + er;
#pragma unroll
    for (int ns = 0; ns < 16; ns++) {
        const int col = h * HDIM + ns * 8 + ec;
        *(__half2*)(g_Ah + (size_t)row * HIDN + col) =
            __floats2half2_rn(o[ns][0] * inv0, o[ns][1] * inv0);
        *(__half2*)(g_Ah + (size_t)(row + 8) * HIDN + col) =
            __floats2half2_rn(o[ns][2] * inv1, o[ns][3] * inv1);
    }
}

// ---------------------------------------------------------------------------
extern "C" void kernel_launch(void* const* d_in, const int* in_sizes, int n_in,
                              void* d_out, int out_size)
{
    const float* X  = (const float*)d_in[0];
    const float* Wq = (const float*)d_in[2];
    const float* Wk = (const float*)d_in[3];
    const float* Wv = (const float*)d_in[4];
    const float* Wo = (const float*)d_in[5];
    float* out = (float*)d_out;

    float *dQ, *dK, *dV;
    cudaGetSymbolAddress((void**)&dQ, g_Q);
    cudaGetSymbolAddress((void**)&dK, g_K);
    cudaGetSymbolAddress((void**)&dV, g_V);
    __half *xh, *ah, *qh, *ql, *kh, *kl, *vh, *vl, *oh, *ol;
    cudaGetSymbolAddress((void**)&xh, g_Xh);
    cudaGetSymbolAddress((void**)&ah, g_Ah);
    cudaGetSymbolAddress((void**)&qh, g_Wqh); cudaGetSymbolAddress((void**)&ql, g_Wql);
    cudaGetSymbolAddress((void**)&kh, g_Wkh); cudaGetSymbolAddress((void**)&kl, g_Wkl);
    cudaGetSymbolAddress((void**)&vh, g_Wvh); cudaGetSymbolAddress((void**)&vl, g_Wvl);
    cudaGetSymbolAddress((void**)&oh, g_Woh); cudaGetSymbolAddress((void**)&ol, g_Wol);

    rope_table<<<(S_LEN * 64) / 256, 256>>>();

    const int nX4 = S_LEN * HIDN / 4, nW4 = HIDN * HIDN / 4;
    split_round<<<nX4 / 256, 256>>>(X, xh);
    split_hilo<<<nW4 / 256, 256>>>(Wq, qh, ql);
    split_hilo<<<nW4 / 256, 256>>>(Wk, kh, kl);
    split_hilo<<<nW4 / 256, 256>>>(Wv, vh, vl);
    split_hilo<<<nW4 / 256, 256>>>(Wo, oh, ol);

    cudaFuncSetAttribute(gemm_f16, cudaFuncAttributeMaxDynamicSharedMemorySize, GEMM_SMEM);
    const dim3 gg(HIDN / 128, S_LEN / 128);
    gemm_f16<<<gg, 128, GEMM_SMEM>>>(xh, qh, ql, dQ);
    gemm_f16<<<gg, 128, GEMM_SMEM>>>(xh, kh, kl, dK);
    gemm_f16<<<gg, 128, GEMM_SMEM>>>(xh, vh, vl, dV);

    rope_split<<<(S_LEN * NHEAD * 64) / 256, 256>>>();
    vt_split<<<(NHEAD * HDIM * S_LEN) / 256, 256>>>();

    cudaFuncSetAttribute(flash_mma, cudaFuncAttributeMaxDynamicSharedMemorySize, FLASH_SMEM_B);
    flash_mma<<<dim3(S_LEN / 128, NHEAD), 256, FLASH_SMEM_B>>>();

    gemm_f16<<<gg, 128, GEMM_SMEM>>>(ah, oh, ol, out);
}

// round 16
// speedup vs baseline: 2.3947x; 1.0418x over previous
#include <cuda_runtime.h>
#include <cuda_fp16.h>
#include <cstdint>
#include <math.h>

#define S_LEN 2048
#define HIDN  4096
#define NHEAD 32
#define HDIM  128

// ------------------------------ scratch (static, allocation-free) ----------
__device__ float g_Q[S_LEN * HIDN];
__device__ float g_K[S_LEN * HIDN];
__device__ float g_V[S_LEN * HIDN];
__device__ float g_cs[S_LEN * 64];
__device__ float g_sn[S_LEN * 64];

// fp16 operands (pre-split, hot loops are conversion-free)
__device__ __half g_Xh[S_LEN * HIDN];                       // X rounded (A-side)
__device__ __half g_Ah[S_LEN * HIDN];                       // attn out rounded
__device__ __half g_Wqh[HIDN * HIDN], g_Wql[HIDN * HIDN];
__device__ __half g_Wkh[HIDN * HIDN], g_Wkl[HIDN * HIDN];
__device__ __half g_Wvh[HIDN * HIDN], g_Wvl[HIDN * HIDN];
__device__ __half g_Woh[HIDN * HIDN], g_Wol[HIDN * HIDN];
__device__ __half g_Qh[S_LEN * HIDN];
__device__ __half g_Kh[S_LEN * HIDN], g_Kl[S_LEN * HIDN];
__device__ __half g_Vth[NHEAD * HDIM * S_LEN], g_Vtl[NHEAD * HDIM * S_LEN];

// ------------------------------ helpers ------------------------------------
__device__ __forceinline__ uint32_t smem_u32(const void* p) {
    uint32_t a;
    asm("{ .reg .u64 t; cvta.to.shared.u64 t, %1; cvt.u32.u64 %0, t; }"
        : "=r"(a) : "l"(p));
    return a;
}

#define LDSM_X4(r, addr)                                                      \
    asm volatile("ldmatrix.sync.aligned.m8n8.x4.shared.b16 {%0,%1,%2,%3}, [%4];" \
        : "=r"((r)[0]), "=r"((r)[1]), "=r"((r)[2]), "=r"((r)[3]) : "r"(addr))

#define MMA_F16(d, a, b0, b1)                                                 \
    asm volatile("mma.sync.aligned.m16n8k16.row.col.f32.f16.f16.f32 "         \
        "{%0,%1,%2,%3}, {%4,%5,%6,%7}, {%8,%9}, {%0,%1,%2,%3};"               \
        : "+f"((d)[0]), "+f"((d)[1]), "+f"((d)[2]), "+f"((d)[3])              \
        : "r"((a)[0]), "r"((a)[1]), "r"((a)[2]), "r"((a)[3]),                 \
          "r"(b0), "r"(b1))

#define CP_ASYNC16(sm, gp)                                                    \
    asm volatile("cp.async.cg.shared.global [%0], [%1], 16;"                  \
                 :: "r"(sm), "l"(gp))
#define CP_COMMIT() asm volatile("cp.async.commit_group;" ::: "memory")
#define CP_WAIT0()  asm volatile("cp.async.wait_group 0;" ::: "memory")

__device__ __forceinline__ void cvt_h4(float4 v, uint2& h)
{
    __half h0 = __float2half_rn(v.x), h1 = __float2half_rn(v.y);
    __half h2 = __float2half_rn(v.z), h3 = __float2half_rn(v.w);
    h.x = (uint32_t)*(unsigned short*)&h0 | ((uint32_t)*(unsigned short*)&h1 << 16);
    h.y = (uint32_t)*(unsigned short*)&h2 | ((uint32_t)*(unsigned short*)&h3 << 16);
}

__device__ __forceinline__ void cvt_hilo(float4 v, uint2& h, uint2& l)
{
    __half h0 = __float2half_rn(v.x), h1 = __float2half_rn(v.y);
    __half h2 = __float2half_rn(v.z), h3 = __float2half_rn(v.w);
    __half l0 = __float2half_rn(v.x - __half2float(h0));
    __half l1 = __float2half_rn(v.y - __half2float(h1));
    __half l2 = __float2half_rn(v.z - __half2float(h2));
    __half l3 = __float2half_rn(v.w - __half2float(h3));
    h.x = (uint32_t)*(unsigned short*)&h0 | ((uint32_t)*(unsigned short*)&h1 << 16);
    h.y = (uint32_t)*(unsigned short*)&h2 | ((uint32_t)*(unsigned short*)&h3 << 16);
    l.x = (uint32_t)*(unsigned short*)&l0 | ((uint32_t)*(unsigned short*)&l1 << 16);
    l.y = (uint32_t)*(unsigned short*)&l2 | ((uint32_t)*(unsigned short*)&l3 << 16);
}

// ------------------------------ split kernels -------------------------------
__global__ void __launch_bounds__(256)
split_round(const float* __restrict__ src, __half* __restrict__ dst)
{
    const int i = blockIdx.x * blockDim.x + threadIdx.x;
    const float4 v = *(const float4*)(src + 4 * (size_t)i);
    uint2 h;
    cvt_h4(v, h);
    *(uint2*)(dst + 4 * (size_t)i) = h;
}

__global__ void __launch_bounds__(256)
split_hilo(const float* __restrict__ src, __half* __restrict__ hi,
           __half* __restrict__ lo)
{
    const int i = blockIdx.x * blockDim.x + threadIdx.x;
    const float4 v = *(const float4*)(src + 4 * (size_t)i);
    uint2 h, l;
    cvt_hilo(v, h, l);
    *(uint2*)(hi + 4 * (size_t)i) = h;
    *(uint2*)(lo + 4 * (size_t)i) = l;
}

// ------------------------------ HMMA fp16 2-term GEMM (cp.async, KC=32) ----
// C[m,n] = sum_k A[m,k]*B[n,k] via Ah·Bh + Ah·Bl, operands pre-split fp16.
// CTA: 128x128, 128 thr = 4 warps (2x2), warp tile 64x64, KC=32, 2-stage pipe,
// 2 CTAs/SM. 128 MMAs per warp per chunk vs one wait+barrier.
#define KC    32
#define PITCH 40
#define TILE_ELEMS (128 * PITCH)
#define TILE_BYTES (TILE_ELEMS * 2)       // 10240
#define BUF_BYTES  (3 * TILE_BYTES)       // Ah, Bh, Bl = 30720
#define GEMM_SMEM  (2 * BUF_BYTES)        // 61440

__global__ void __launch_bounds__(128, 2)
gemm_f16(const __half* __restrict__ Ag, const __half* __restrict__ Bhg,
         const __half* __restrict__ Blg, float* __restrict__ C)
{
    extern __shared__ char smraw[];
    const uint32_t smb = smem_u32(smraw);

    const int tid  = threadIdx.x;
    const int lane = tid & 31;
    const int wid  = tid >> 5;
    const int wm   = wid & 1;
    const int wn   = wid >> 1;
    const int m0   = blockIdx.y << 7;
    const int n0   = blockIdx.x << 7;

    float acc[4][8][4];
#pragma unroll
    for (int i = 0; i < 4; i++)
#pragma unroll
        for (int j = 0; j < 8; j++)
#pragma unroll
            for (int r = 0; r < 4; r++) acc[i][j][r] = 0.f;

    // cp.async loader: 1536 x 16B per chunk (3 tiles x 128 rows x 4 col-blocks)
    auto load_chunk = [&](int k0, int b) {
        const uint32_t base = smb + b * BUF_BYTES;
#pragma unroll
        for (int i = 0; i < 12; i++) {
            const int idx  = tid + i * 128;        // 0..1535
            const int tile = idx >> 9;             // 0..2
            const int q    = idx & 511;
            const int r    = q >> 2;               // 0..127
            const int cb   = (q & 3) << 3;         // 0,8,16,24
            const __half* gp =
                (tile == 0) ? Ag  + (size_t)(m0 + r) * HIDN + k0 + cb :
                (tile == 1) ? Bhg + (size_t)(n0 + r) * HIDN + k0 + cb :
                              Blg + (size_t)(n0 + r) * HIDN + k0 + cb;
            const uint32_t sm = base + tile * TILE_BYTES + (r * PITCH + cb) * 2;
            CP_ASYNC16(sm, gp);
        }
    };

    auto compute = [&](int b) {
        const uint32_t base = smb + b * BUF_BYTES;
        const uint32_t Ah = base;
        const uint32_t Bh = base + TILE_BYTES;
        const uint32_t Bl = base + 2 * TILE_BYTES;

        const int arow = wm * 64 + (lane & 15);
        const int acol = (lane >> 4) << 3;
        const int brow = wn * 64 + ((lane >> 4) << 3) + (lane & 7);
        const int bcol = ((lane >> 3) & 1) << 3;

#pragma unroll
        for (int ks = 0; ks < 2; ks++) {
            uint32_t ah[4][4];
#pragma unroll
            for (int ms = 0; ms < 4; ms++) {
                const uint32_t off = ((arow + ms * 16) * PITCH + ks * 16 + acol) * 2;
                LDSM_X4(ah[ms], Ah + off);
            }
#pragma unroll
            for (int p = 0; p < 4; p++) {
                uint32_t bh[4], bl[4];
                const uint32_t off = ((brow + p * 16) * PITCH + ks * 16 + bcol) * 2;
                LDSM_X4(bh, Bh + off);
                LDSM_X4(bl, Bl + off);
#pragma unroll
                for (int ms = 0; ms < 4; ms++)
#pragma unroll
                    for (int hf = 0; hf < 2; hf++) {
                        const int ns = p * 2 + hf;
                        MMA_F16(acc[ms][ns], ah[ms], bh[hf * 2], bh[hf * 2 + 1]);
                        MMA_F16(acc[ms][ns], ah[ms], bl[hf * 2], bl[hf * 2 + 1]);
                    }
            }
        }
    };

    load_chunk(0, 0);
    CP_COMMIT();

    const int NCHUNK = HIDN / KC;   // 128
    for (int c = 0; c < NCHUNK; c++) {
        CP_WAIT0();
        __syncthreads();            // chunk c visible; prev compute done
        if (c + 1 < NCHUNK) {
            load_chunk((c + 1) * KC, (c + 1) & 1);
            CP_COMMIT();
        }
        compute(c & 1);
    }

    const int er = lane >> 2;
    const int ec = (lane & 3) << 1;
#pragma unroll
    for (int ms = 0; ms < 4; ms++) {
        const int row = m0 + wm * 64 + ms * 16 + er;
#pragma unroll
        for (int ns = 0; ns < 8; ns++) {
            const int col = n0 + wn * 64 + ns * 8 + ec;
            *(float2*)(C + (size_t)row * HIDN + col) =
                make_float2(acc[ms][ns][0], acc[ms][ns][1]);
            *(float2*)(C + (size_t)(row + 8) * HIDN + col) =
                make_float2(acc[ms][ns][2], acc[ms][ns][3]);
        }
    }
}

// ------------------------------ rope table (double trig; fast-math-safe) ---
__global__ void __launch_bounds__(256)
rope_table()
{
    const int idx = blockIdx.x * blockDim.x + threadIdx.x;
    const int j = idx & 63;
    const int s = idx >> 6;
    const float invf = (float)pow(10000.0, -(double)(2 * j) / 128.0);
    const float ang  = (float)s * invf;
    g_cs[idx] = (float)cos((double)ang);
    g_sn[idx] = (float)sin((double)ang);
}

// ---- fused: half-split rope on Q,K; Q rounded to fp16, K split hi/lo ------
__global__ void __launch_bounds__(256)
rope_split()
{
    const int idx = blockIdx.x * blockDim.x + threadIdx.x;   // < 4,194,304
    const int j = idx & 63;
    const int h = (idx >> 6) & 31;
    const int s = idx >> 11;
    const float cs = g_cs[(s << 6) + j];
    const float sn = g_sn[(s << 6) + j];
    const size_t base = (size_t)s * HIDN + h * HDIM + j;

    const float q0 = g_Q[base], q1 = g_Q[base + 64];
    g_Qh[base]      = __float2half_rn(q0 * cs - q1 * sn);
    g_Qh[base + 64] = __float2half_rn(q1 * cs + q0 * sn);

    const float k0 = g_K[base], k1 = g_K[base + 64];
    float a = k0 * cs - k1 * sn;
    float b = k1 * cs + k0 * sn;
    __half hh = __float2half_rn(a);
    g_Kh[base] = hh; g_Kl[base] = __float2half_rn(a - __half2float(hh));
    hh = __float2half_rn(b);
    g_Kh[base + 64] = hh; g_Kl[base + 64] = __float2half_rn(b - __half2float(hh));
}

// ---- V: per-head transpose + fp16 hi/lo split: g_Vth[h][d][s] -------------
__global__ void __launch_bounds__(256)
vt_split()
{
    const int idx = blockIdx.x * blockDim.x + threadIdx.x;   // < 8,388,608
    const int s = idx & 2047;
    const int d = (idx >> 11) & 127;
    const int h = idx >> 18;
    const float v = g_V[(size_t)s * HIDN + h * HDIM + d];
    const __half hi = __float2half_rn(v);
    const size_t o = (size_t)h * (HDIM * S_LEN) + (size_t)d * S_LEN + s;
    g_Vth[o] = hi;
    g_Vtl[o] = __float2half_rn(v - __half2float(hi));
}

// ------------------------------ flash attention (HMMA fp16 2-term) ---------
#define FQP 136
#define FVP 72
#define OFF_QH 0
#define OFF_KH 17408
#define OFF_KL 26112
#define OFF_VH 34816
#define OFF_VL 44032
#define OFF_PH 53248
#define FLASH_SMEM_B (62464 * 2)

__global__ void __launch_bounds__(256, 1)
flash_mma()
{
    extern __shared__ __half fsm[];
    const uint32_t smb = smem_u32(fsm);
    const int tid  = threadIdx.x;
    const int lane = tid & 31;
    const int w    = tid >> 5;
    const int h    = blockIdx.y;
    const int q0   = blockIdx.x << 7;

#pragma unroll
    for (int i = 0; i < 8; i++) {
        const int idx = tid + i * 256;
        const int row = idx >> 4;
        const int col = (idx & 15) << 3;
        const size_t g = (size_t)(q0 + row) * HIDN + h * HDIM + col;
        *(uint4*)&fsm[OFF_QH + row * FQP + col] = *(const uint4*)&g_Qh[g];
    }

    float o[16][4];
#pragma unroll
    for (int i = 0; i < 16; i++)
#pragma unroll
        for (int r = 0; r < 4; r++) o[i][r] = 0.f;
    float mrow[2] = {-1e30f, -1e30f};
    float lrow[2] = {0.f, 0.f};

    const int er = lane >> 2;
    const int ec = (lane & 3) << 1;
    const int nkt = (q0 >> 6) + 2;

    for (int kt = 0; kt < nkt; kt++) {
        const int k0 = kt << 6;
        __syncthreads();
#pragma unroll
        for (int i = 0; i < 4; i++) {
            const int idx = tid + i * 256;
            {
                const int row = idx >> 4;
                const int col = (idx & 15) << 3;
                const size_t g = (size_t)(k0 + row) * HIDN + h * HDIM + col;
                *(uint4*)&fsm[OFF_KH + row * FQP + col] = *(const uint4*)&g_Kh[g];
                *(uint4*)&fsm[OFF_KL + row * FQP + col] = *(const uint4*)&g_Kl[g];
            }
            {
                const int d  = idx >> 3;
                const int sb = (idx & 7) << 3;
                const size_t g = (size_t)h * (HDIM * S_LEN) + (size_t)d * S_LEN + k0 + sb;
                *(uint4*)&fsm[OFF_VH + d * FVP + sb] = *(const uint4*)&g_Vth[g];
                *(uint4*)&fsm[OFF_VL + d * FVP + sb] = *(const uint4*)&g_Vtl[g];
            }
        }
        __syncthreads();

        float s[8][4];
#pragma unroll
        for (int i = 0; i < 8; i++)
#pragma unroll
            for (int r = 0; r < 4; r++) s[i][r] = 0.f;

        const int arow = w * 16 + (lane & 15);
        const int acol8 = (lane >> 4) << 3;
        const int brow = ((lane >> 4) << 3) + (lane & 7);
        const int bcol8 = ((lane >> 3) & 1) << 3;
#pragma unroll
        for (int ks = 0; ks < 8; ks++) {
            uint32_t ah[4];
            const uint32_t aoff = (uint32_t)(arow * FQP + ks * 16 + acol8) * 2;
            LDSM_X4(ah, smb + OFF_QH * 2 + aoff);
#pragma unroll
            for (int p = 0; p < 4; p++) {
                uint32_t bh[4], bl[4];
                const uint32_t boff =
                    (uint32_t)((p * 16 + brow) * FQP + ks * 16 + bcol8) * 2;
                LDSM_X4(bh, smb + OFF_KH * 2 + boff);
                LDSM_X4(bl, smb + OFF_KL * 2 + boff);
#pragma unroll
                for (int hf = 0; hf < 2; hf++) {
                    const int ns = p * 2 + hf;
                    MMA_F16(s[ns], ah, bh[hf * 2], bh[hf * 2 + 1]);
                    MMA_F16(s[ns], ah, bl[hf * 2], bl[hf * 2 + 1]);
                }
            }
        }

        const float sc = 0.08838834764831845f;
        const bool diag = (k0 + 63 > q0);
        const uint32_t pwarp = (uint32_t)(w * 16 * FVP);
#pragma unroll
        for (int i = 0; i < 2; i++) {
            const int qg = q0 + w * 16 + er + 8 * i;
            float rmax = -1e30f;
#pragma unroll
            for (int ns = 0; ns < 8; ns++)
#pragma unroll
                for (int c = 0; c < 2; c++) {
                    float v = s[ns][i * 2 + c] * sc;
                    if (diag && (k0 + ns * 8 + ec + c > qg)) v = -1e30f;
                    s[ns][i * 2 + c] = v;
                    rmax = fmaxf(rmax, v);
                }
            rmax = fmaxf(rmax, __shfl_xor_sync(0xffffffffu, rmax, 1));
            rmax = fmaxf(rmax, __shfl_xor_sync(0xffffffffu, rmax, 2));
            const float mn = fmaxf(mrow[i], rmax);
            const float corr = __expf(mrow[i] - mn);
            mrow[i] = mn;
            float rs = 0.f;
#pragma unroll
            for (int ns = 0; ns < 8; ns++) {
                const float p0 = __expf(s[ns][i * 2 + 0] - mn);
                const float p1 = __expf(s[ns][i * 2 + 1] - mn);
                rs += p0 + p1;
                __half h0 = __float2half_rn(p0);
                __half h1 = __float2half_rn(p1);
                const uint32_t hp = (uint32_t)*(unsigned short*)&h0
                                  | ((uint32_t)*(unsigned short*)&h1 << 16);
                const int pr = er + 8 * i;
                *(uint32_t*)&fsm[OFF_PH + pwarp + pr * FVP + ns * 8 + ec] = hp;
            }
            rs += __shfl_xor_sync(0xffffffffu, rs, 1);
            rs += __shfl_xor_sync(0xffffffffu, rs, 2);
            lrow[i] = lrow[i] * corr + rs;
#pragma unroll
            for (int ns = 0; ns < 16; ns++) {
                o[ns][i * 2 + 0] *= corr;
                o[ns][i * 2 + 1] *= corr;
            }
        }
        __syncwarp();

#pragma unroll
        for (int ks = 0; ks < 4; ks++) {
            uint32_t pah[4];
            const uint32_t aoff =
                pwarp * 2 + (uint32_t)((lane & 15) * FVP + ks * 16 + acol8) * 2;
            LDSM_X4(pah, smb + OFF_PH * 2 + aoff);
#pragma unroll
            for (int p = 0; p < 8; p++) {
                uint32_t bh[4], bl[4];
                const uint32_t boff =
                    (uint32_t)((p * 16 + brow) * FVP + ks * 16 + bcol8) * 2;
                LDSM_X4(bh, smb + OFF_VH * 2 + boff);
                LDSM_X4(bl, smb + OFF_VL * 2 + boff);
#pragma unroll
                for (int hf = 0; hf < 2; hf++) {
                    const int ns = p * 2 + hf;
                    MMA_F16(o[ns], pah, bh[hf * 2], bh[hf * 2 + 1]);
                    MMA_F16(o[ns], pah, bl[hf * 2], bl[hf * 2 + 1]);
                }
            }
        }
    }

    // epilogue: write attention output directly as fp16 (A-side of final GEMM)
    const float inv0 = 1.0f / lrow[0];
    const float inv1 = 1.0f / lrow[1];
    const int row = q0 + w * 16 + er;
#pragma unroll
    for (int ns = 0; ns < 16; ns++) {
        const int col = h * HDIM + ns * 8 + ec;
        *(__half2*)(g_Ah + (size_t)row * HIDN + col) =
            __floats2half2_rn(o[ns][0] * inv0, o[ns][1] * inv0);
        *(__half2*)(g_Ah + (size_t)(row + 8) * HIDN + col) =
            __floats2half2_rn(o[ns][2] * inv1, o[ns][3] * inv1);
    }
}

// ---------------------------------------------------------------------------
extern "C" void kernel_launch(void* const* d_in, const int* in_sizes, int n_in,
                              void* d_out, int out_size)
{
    const float* X  = (const float*)d_in[0];
    const float* Wq = (const float*)d_in[2];
    const float* Wk = (const float*)d_in[3];
    const float* Wv = (const float*)d_in[4];
    const float* Wo = (const float*)d_in[5];
    float* out = (float*)d_out;

    float *dQ, *dK, *dV;
    cudaGetSymbolAddress((void**)&dQ, g_Q);
    cudaGetSymbolAddress((void**)&dK, g_K);
    cudaGetSymbolAddress((void**)&dV, g_V);
    __half *xh, *ah, *qh, *ql, *kh, *kl, *vh, *vl, *oh, *ol;
    cudaGetSymbolAddress((void**)&xh, g_Xh);
    cudaGetSymbolAddress((void**)&ah, g_Ah);
    cudaGetSymbolAddress((void**)&qh, g_Wqh); cudaGetSymbolAddress((void**)&ql, g_Wql);
    cudaGetSymbolAddress((void**)&kh, g_Wkh); cudaGetSymbolAddress((void**)&kl, g_Wkl);
    cudaGetSymbolAddress((void**)&vh, g_Wvh); cudaGetSymbolAddress((void**)&vl, g_Wvl);
    cudaGetSymbolAddress((void**)&oh, g_Woh); cudaGetSymbolAddress((void**)&ol, g_Wol);

    rope_table<<<(S_LEN * 64) / 256, 256>>>();

    const int nX4 = S_LEN * HIDN / 4, nW4 = HIDN * HIDN / 4;
    split_round<<<nX4 / 256, 256>>>(X, xh);
    split_hilo<<<nW4 / 256, 256>>>(Wq, qh, ql);
    split_hilo<<<nW4 / 256, 256>>>(Wk, kh, kl);
    split_hilo<<<nW4 / 256, 256>>>(Wv, vh, vl);
    split_hilo<<<nW4 / 256, 256>>>(Wo, oh, ol);

    cudaFuncSetAttribute(gemm_f16, cudaFuncAttributeMaxDynamicSharedMemorySize, GEMM_SMEM);
    const dim3 gg(HIDN / 128, S_LEN / 128);
    gemm_f16<<<gg, 128, GEMM_SMEM>>>(xh, qh, ql, dQ);
    gemm_f16<<<gg, 128, GEMM_SMEM>>>(xh, kh, kl, dK);
    gemm_f16<<<gg, 128, GEMM_SMEM>>>(xh, vh, vl, dV);

    rope_split<<<(S_LEN * NHEAD * 64) / 256, 256>>>();
    vt_split<<<(NHEAD * HDIM * S_LEN) / 256, 256>>>();

    cudaFuncSetAttribute(flash_mma, cudaFuncAttributeMaxDynamicSharedMemorySize, FLASH_SMEM_B);
    flash_mma<<<dim3(S_LEN / 128, NHEAD), 256, FLASH_SMEM_B>>>();

    gemm_f16<<<gg, 128, GEMM_SMEM>>>(ah, oh, ol, out);
}

// round 17
// speedup vs baseline: 2.3968x; 1.0009x over previous
#include <cuda_runtime.h>
#include <cuda_fp16.h>
#include <cstdint>
#include <math.h>

#define S_LEN 2048
#define HIDN  4096
#define NHEAD 32
#define HDIM  128

// ------------------------------ scratch (static, allocation-free) ----------
__device__ float g_Q[S_LEN * HIDN];
__device__ float g_K[S_LEN * HIDN];
__device__ float g_V[S_LEN * HIDN];
__device__ float g_cs[S_LEN * 64];
__device__ float g_sn[S_LEN * 64];

// fp16 operands (pre-split, hot loops are conversion-free)
__device__ __half g_Xh[S_LEN * HIDN];
__device__ __half g_Ah[S_LEN * HIDN];
__device__ __half g_Wqh[HIDN * HIDN], g_Wql[HIDN * HIDN];
__device__ __half g_Wkh[HIDN * HIDN], g_Wkl[HIDN * HIDN];
__device__ __half g_Wvh[HIDN * HIDN], g_Wvl[HIDN * HIDN];
__device__ __half g_Woh[HIDN * HIDN], g_Wol[HIDN * HIDN];
__device__ __half g_Qh[S_LEN * HIDN];
__device__ __half g_Kh[S_LEN * HIDN], g_Kl[S_LEN * HIDN];
__device__ __half g_Vth[NHEAD * HDIM * S_LEN], g_Vtl[NHEAD * HDIM * S_LEN];

// ------------------------------ helpers ------------------------------------
__device__ __forceinline__ uint32_t smem_u32(const void* p) {
    uint32_t a;
    asm("{ .reg .u64 t; cvta.to.shared.u64 t, %1; cvt.u32.u64 %0, t; }"
        : "=r"(a) : "l"(p));
    return a;
}

#define LDSM_X4(r, addr)                                                      \
    asm volatile("ldmatrix.sync.aligned.m8n8.x4.shared.b16 {%0,%1,%2,%3}, [%4];" \
        : "=r"((r)[0]), "=r"((r)[1]), "=r"((r)[2]), "=r"((r)[3]) : "r"(addr))

#define MMA_F16(d, a, b0, b1)                                                 \
    asm volatile("mma.sync.aligned.m16n8k16.row.col.f32.f16.f16.f32 "         \
        "{%0,%1,%2,%3}, {%4,%5,%6,%7}, {%8,%9}, {%0,%1,%2,%3};"               \
        : "+f"((d)[0]), "+f"((d)[1]), "+f"((d)[2]), "+f"((d)[3])              \
        : "r"((a)[0]), "r"((a)[1]), "r"((a)[2]), "r"((a)[3]),                 \
          "r"(b0), "r"(b1))

#define CP_ASYNC16(sm, gp)                                                    \
    asm volatile("cp.async.cg.shared.global [%0], [%1], 16;"                  \
                 :: "r"(sm), "l"(gp))
#define CP_COMMIT() asm volatile("cp.async.commit_group;" ::: "memory")
#define CP_WAIT0()  asm volatile("cp.async.wait_group 0;" ::: "memory")

__device__ __forceinline__ void cvt_h4(float4 v, uint2& h)
{
    __half h0 = __float2half_rn(v.x), h1 = __float2half_rn(v.y);
    __half h2 = __float2half_rn(v.z), h3 = __float2half_rn(v.w);
    h.x = (uint32_t)*(unsigned short*)&h0 | ((uint32_t)*(unsigned short*)&h1 << 16);
    h.y = (uint32_t)*(unsigned short*)&h2 | ((uint32_t)*(unsigned short*)&h3 << 16);
}

__device__ __forceinline__ void cvt_hilo(float4 v, uint2& h, uint2& l)
{
    __half h0 = __float2half_rn(v.x), h1 = __float2half_rn(v.y);
    __half h2 = __float2half_rn(v.z), h3 = __float2half_rn(v.w);
    __half l0 = __float2half_rn(v.x - __half2float(h0));
    __half l1 = __float2half_rn(v.y - __half2float(h1));
    __half l2 = __float2half_rn(v.z - __half2float(h2));
    __half l3 = __float2half_rn(v.w - __half2float(h3));
    h.x = (uint32_t)*(unsigned short*)&h0 | ((uint32_t)*(unsigned short*)&h1 << 16);
    h.y = (uint32_t)*(unsigned short*)&h2 | ((uint32_t)*(unsigned short*)&h3 << 16);
    l.x = (uint32_t)*(unsigned short*)&l0 | ((uint32_t)*(unsigned short*)&l1 << 16);
    l.y = (uint32_t)*(unsigned short*)&l2 | ((uint32_t)*(unsigned short*)&l3 << 16);
}

// ------------------------------ split kernels -------------------------------
__global__ void __launch_bounds__(256)
split_round(const float* __restrict__ src, __half* __restrict__ dst)
{
    const int i = blockIdx.x * blockDim.x + threadIdx.x;
    const float4 v = *(const float4*)(src + 4 * (size_t)i);
    uint2 h;
    cvt_h4(v, h);
    *(uint2*)(dst + 4 * (size_t)i) = h;
}

__global__ void __launch_bounds__(256)
split_hilo(const float* __restrict__ src, __half* __restrict__ hi,
           __half* __restrict__ lo)
{
    const int i = blockIdx.x * blockDim.x + threadIdx.x;
    const float4 v = *(const float4*)(src + 4 * (size_t)i);
    uint2 h, l;
    cvt_hilo(v, h, l);
    *(uint2*)(hi + 4 * (size_t)i) = h;
    *(uint2*)(lo + 4 * (size_t)i) = l;
}

// ------------------------------ HMMA fp16 2-term GEMM (cp.async, KC=32) ----
// hi/lo MMA sweeps separated: adjacent MMAs never share an accumulator
// (8-op reuse distance), per-accumulator order unchanged (bit-identical).
#define KC    32
#define PITCH 40
#define TILE_ELEMS (128 * PITCH)
#define TILE_BYTES (TILE_ELEMS * 2)       // 10240
#define BUF_BYTES  (3 * TILE_BYTES)       // 30720
#define GEMM_SMEM  (2 * BUF_BYTES)        // 61440

__global__ void __launch_bounds__(128, 2)
gemm_f16(const __half* __restrict__ Ag, const __half* __restrict__ Bhg,
         const __half* __restrict__ Blg, float* __restrict__ C)
{
    extern __shared__ char smraw[];
    const uint32_t smb = smem_u32(smraw);

    const int tid  = threadIdx.x;
    const int lane = tid & 31;
    const int wid  = tid >> 5;
    const int wm   = wid & 1;
    const int wn   = wid >> 1;
    const int m0   = blockIdx.y << 7;
    const int n0   = blockIdx.x << 7;

    float acc[4][8][4];
#pragma unroll
    for (int i = 0; i < 4; i++)
#pragma unroll
        for (int j = 0; j < 8; j++)
#pragma unroll
            for (int r = 0; r < 4; r++) acc[i][j][r] = 0.f;

    auto load_chunk = [&](int k0, int b) {
        const uint32_t base = smb + b * BUF_BYTES;
#pragma unroll
        for (int i = 0; i < 12; i++) {
            const int idx  = tid + i * 128;
            const int tile = idx >> 9;
            const int q    = idx & 511;
            const int r    = q >> 2;
            const int cb   = (q & 3) << 3;
            const __half* gp =
                (tile == 0) ? Ag  + (size_t)(m0 + r) * HIDN + k0 + cb :
                (tile == 1) ? Bhg + (size_t)(n0 + r) * HIDN + k0 + cb :
                              Blg + (size_t)(n0 + r) * HIDN + k0 + cb;
            const uint32_t sm = base + tile * TILE_BYTES + (r * PITCH + cb) * 2;
            CP_ASYNC16(sm, gp);
        }
    };

    auto compute = [&](int b) {
        const uint32_t base = smb + b * BUF_BYTES;
        const uint32_t Ah = base;
        const uint32_t Bh = base + TILE_BYTES;
        const uint32_t Bl = base + 2 * TILE_BYTES;

        const int arow = wm * 64 + (lane & 15);
        const int acol = (lane >> 4) << 3;
        const int brow = wn * 64 + ((lane >> 4) << 3) + (lane & 7);
        const int bcol = ((lane >> 3) & 1) << 3;

#pragma unroll
        for (int ks = 0; ks < 2; ks++) {
            uint32_t ah[4][4];
#pragma unroll
            for (int ms = 0; ms < 4; ms++) {
                const uint32_t off = ((arow + ms * 16) * PITCH + ks * 16 + acol) * 2;
                LDSM_X4(ah[ms], Ah + off);
            }
#pragma unroll
            for (int p = 0; p < 4; p++) {
                uint32_t bh[4], bl[4];
                const uint32_t off = ((brow + p * 16) * PITCH + ks * 16 + bcol) * 2;
                LDSM_X4(bh, Bh + off);
                LDSM_X4(bl, Bl + off);
                // pass 1: hi sweep (8 distinct accumulators)
#pragma unroll
                for (int ms = 0; ms < 4; ms++)
#pragma unroll
                    for (int hf = 0; hf < 2; hf++)
                        MMA_F16(acc[ms][p * 2 + hf], ah[ms],
                                bh[hf * 2], bh[hf * 2 + 1]);
                // pass 2: lo sweep (same order -> per-acc sequence unchanged)
#pragma unroll
                for (int ms = 0; ms < 4; ms++)
#pragma unroll
                    for (int hf = 0; hf < 2; hf++)
                        MMA_F16(acc[ms][p * 2 + hf], ah[ms],
                                bl[hf * 2], bl[hf * 2 + 1]);
            }
        }
    };

    load_chunk(0, 0);
    CP_COMMIT();

    const int NCHUNK = HIDN / KC;
    for (int c = 0; c < NCHUNK; c++) {
        CP_WAIT0();
        __syncthreads();
        if (c + 1 < NCHUNK) {
            load_chunk((c + 1) * KC, (c + 1) & 1);
            CP_COMMIT();
        }
        compute(c & 1);
    }

    const int er = lane >> 2;
    const int ec = (lane & 3) << 1;
#pragma unroll
    for (int ms = 0; ms < 4; ms++) {
        const int row = m0 + wm * 64 + ms * 16 + er;
#pragma unroll
        for (int ns = 0; ns < 8; ns++) {
            const int col = n0 + wn * 64 + ns * 8 + ec;
            *(float2*)(C + (size_t)row * HIDN + col) =
                make_float2(acc[ms][ns][0], acc[ms][ns][1]);
            *(float2*)(C + (size_t)(row + 8) * HIDN + col) =
                make_float2(acc[ms][ns][2], acc[ms][ns][3]);
        }
    }
}

// ------------------------------ rope table (double trig; fast-math-safe) ---
__global__ void __launch_bounds__(256)
rope_table()
{
    const int idx = blockIdx.x * blockDim.x + threadIdx.x;
    const int j = idx & 63;
    const int s = idx >> 6;
    const float invf = (float)pow(10000.0, -(double)(2 * j) / 128.0);
    const float ang  = (float)s * invf;
    g_cs[idx] = (float)cos((double)ang);
    g_sn[idx] = (float)sin((double)ang);
}

__global__ void __launch_bounds__(256)
rope_split()
{
    const int idx = blockIdx.x * blockDim.x + threadIdx.x;
    const int j = idx & 63;
    const int h = (idx >> 6) & 31;
    const int s = idx >> 11;
    const float cs = g_cs[(s << 6) + j];
    const float sn = g_sn[(s << 6) + j];
    const size_t base = (size_t)s * HIDN + h * HDIM + j;

    const float q0 = g_Q[base], q1 = g_Q[base + 64];
    g_Qh[base]      = __float2half_rn(q0 * cs - q1 * sn);
    g_Qh[base + 64] = __float2half_rn(q1 * cs + q0 * sn);

    const float k0 = g_K[base], k1 = g_K[base + 64];
    float a = k0 * cs - k1 * sn;
    float b = k1 * cs + k0 * sn;
    __half hh = __float2half_rn(a);
    g_Kh[base] = hh; g_Kl[base] = __float2half_rn(a - __half2float(hh));
    hh = __float2half_rn(b);
    g_Kh[base + 64] = hh; g_Kl[base + 64] = __float2half_rn(b - __half2float(hh));
}

__global__ void __launch_bounds__(256)
vt_split()
{
    const int idx = blockIdx.x * blockDim.x + threadIdx.x;
    const int s = idx & 2047;
    const int d = (idx >> 11) & 127;
    const int h = idx >> 18;
    const float v = g_V[(size_t)s * HIDN + h * HDIM + d];
    const __half hi = __float2half_rn(v);
    const size_t o = (size_t)h * (HDIM * S_LEN) + (size_t)d * S_LEN + s;
    g_Vth[o] = hi;
    g_Vtl[o] = __float2half_rn(v - __half2float(hi));
}

// ------------------------------ flash attention (HMMA fp16 2-term) ---------
#define FQP 136
#define FVP 72
#define OFF_QH 0
#define OFF_KH 17408
#define OFF_KL 26112
#define OFF_VH 34816
#define OFF_VL 44032
#define OFF_PH 53248
#define FLASH_SMEM_B (62464 * 2)

__global__ void __launch_bounds__(256, 1)
flash_mma()
{
    extern __shared__ __half fsm[];
    const uint32_t smb = smem_u32(fsm);
    const int tid  = threadIdx.x;
    const int lane = tid & 31;
    const int w    = tid >> 5;
    const int h    = blockIdx.y;
    // reversed mapping: longest (high-q0) CTAs first for tail balance
    const int q0   = (int)(gridDim.x - 1 - blockIdx.x) << 7;

#pragma unroll
    for (int i = 0; i < 8; i++) {
        const int idx = tid + i * 256;
        const int row = idx >> 4;
        const int col = (idx & 15) << 3;
        const size_t g = (size_t)(q0 + row) * HIDN + h * HDIM + col;
        *(uint4*)&fsm[OFF_QH + row * FQP + col] = *(const uint4*)&g_Qh[g];
    }

    float o[16][4];
#pragma unroll
    for (int i = 0; i < 16; i++)
#pragma unroll
        for (int r = 0; r < 4; r++) o[i][r] = 0.f;
    float mrow[2] = {-1e30f, -1e30f};
    float lrow[2] = {0.f, 0.f};

    const int er = lane >> 2;
    const int ec = (lane & 3) << 1;
    const int nkt = (q0 >> 6) + 2;

    for (int kt = 0; kt < nkt; kt++) {
        const int k0 = kt << 6;
        __syncthreads();
#pragma unroll
        for (int i = 0; i < 4; i++) {
            const int idx = tid + i * 256;
            {
                const int row = idx >> 4;
                const int col = (idx & 15) << 3;
                const size_t g = (size_t)(k0 + row) * HIDN + h * HDIM + col;
                *(uint4*)&fsm[OFF_KH + row * FQP + col] = *(const uint4*)&g_Kh[g];
                *(uint4*)&fsm[OFF_KL + row * FQP + col] = *(const uint4*)&g_Kl[g];
            }
            {
                const int d  = idx >> 3;
                const int sb = (idx & 7) << 3;
                const size_t g = (size_t)h * (HDIM * S_LEN) + (size_t)d * S_LEN + k0 + sb;
                *(uint4*)&fsm[OFF_VH + d * FVP + sb] = *(const uint4*)&g_Vth[g];
                *(uint4*)&fsm[OFF_VL + d * FVP + sb] = *(const uint4*)&g_Vtl[g];
            }
        }
        __syncthreads();

        float s[8][4];
#pragma unroll
        for (int i = 0; i < 8; i++)
#pragma unroll
            for (int r = 0; r < 4; r++) s[i][r] = 0.f;

        const int arow = w * 16 + (lane & 15);
        const int acol8 = (lane >> 4) << 3;
        const int brow = ((lane >> 4) << 3) + (lane & 7);
        const int bcol8 = ((lane >> 3) & 1) << 3;
#pragma unroll
        for (int ks = 0; ks < 8; ks++) {
            uint32_t ah[4];
            const uint32_t aoff = (uint32_t)(arow * FQP + ks * 16 + acol8) * 2;
            LDSM_X4(ah, smb + OFF_QH * 2 + aoff);
#pragma unroll
            for (int p = 0; p < 4; p++) {
                uint32_t bh[4], bl[4];
                const uint32_t boff =
                    (uint32_t)((p * 16 + brow) * FQP + ks * 16 + bcol8) * 2;
                LDSM_X4(bh, smb + OFF_KH * 2 + boff);
                LDSM_X4(bl, smb + OFF_KL * 2 + boff);
                MMA_F16(s[p * 2 + 0], ah, bh[0], bh[1]);
                MMA_F16(s[p * 2 + 1], ah, bh[2], bh[3]);
                MMA_F16(s[p * 2 + 0], ah, bl[0], bl[1]);
                MMA_F16(s[p * 2 + 1], ah, bl[2], bl[3]);
            }
        }

        const float sc = 0.08838834764831845f;
        const bool diag = (k0 + 63 > q0);
        const uint32_t pwarp = (uint32_t)(w * 16 * FVP);
#pragma unroll
        for (int i = 0; i < 2; i++) {
            const int qg = q0 + w * 16 + er + 8 * i;
            float rmax = -1e30f;
#pragma unroll
            for (int ns = 0; ns < 8; ns++)
#pragma unroll
                for (int c = 0; c < 2; c++) {
                    float v = s[ns][i * 2 + c] * sc;
                    if (diag && (k0 + ns * 8 + ec + c > qg)) v = -1e30f;
                    s[ns][i * 2 + c] = v;
                    rmax = fmaxf(rmax, v);
                }
            rmax = fmaxf(rmax, __shfl_xor_sync(0xffffffffu, rmax, 1));
            rmax = fmaxf(rmax, __shfl_xor_sync(0xffffffffu, rmax, 2));
            const float mn = fmaxf(mrow[i], rmax);
            const float corr = __expf(mrow[i] - mn);
            mrow[i] = mn;
            float rs = 0.f;
#pragma unroll
            for (int ns = 0; ns < 8; ns++) {
                const float p0 = __expf(s[ns][i * 2 + 0] - mn);
                const float p1 = __expf(s[ns][i * 2 + 1] - mn);
                rs += p0 + p1;
                __half h0 = __float2half_rn(p0);
                __half h1 = __float2half_rn(p1);
                const uint32_t hp = (uint32_t)*(unsigned short*)&h0
                                  | ((uint32_t)*(unsigned short*)&h1 << 16);
                const int pr = er + 8 * i;
                *(uint32_t*)&fsm[OFF_PH + pwarp + pr * FVP + ns * 8 + ec] = hp;
            }
            rs += __shfl_xor_sync(0xffffffffu, rs, 1);
            rs += __shfl_xor_sync(0xffffffffu, rs, 2);
            lrow[i] = lrow[i] * corr + rs;
#pragma unroll
            for (int ns = 0; ns < 16; ns++) {
                o[ns][i * 2 + 0] *= corr;
                o[ns][i * 2 + 1] *= corr;
            }
        }
        __syncwarp();

#pragma unroll
        for (int ks = 0; ks < 4; ks++) {
            uint32_t pah[4];
            const uint32_t aoff =
                pwarp * 2 + (uint32_t)((lane & 15) * FVP + ks * 16 + acol8) * 2;
            LDSM_X4(pah, smb + OFF_PH * 2 + aoff);
#pragma unroll
            for (int p = 0; p < 8; p++) {
                uint32_t bh[4], bl[4];
                const uint32_t boff =
                    (uint32_t)((p * 16 + brow) * FVP + ks * 16 + bcol8) * 2;
                LDSM_X4(bh, smb + OFF_VH * 2 + boff);
                LDSM_X4(bl, smb + OFF_VL * 2 + boff);
                MMA_F16(o[p * 2 + 0], pah, bh[0], bh[1]);
                MMA_F16(o[p * 2 + 1], pah, bh[2], bh[3]);
                MMA_F16(o[p * 2 + 0], pah, bl[0], bl[1]);
                MMA_F16(o[p * 2 + 1], pah, bl[2], bl[3]);
            }
        }
    }

    const float inv0 = 1.0f / lrow[0];
    const float inv1 = 1.0f / lrow[1];
    const int row = q0 + w * 16 + er;
#pragma unroll
    for (int ns = 0; ns < 16; ns++) {
        const int col = h * HDIM + ns * 8 + ec;
        *(__half2*)(g_Ah + (size_t)row * HIDN + col) =
            __floats2half2_rn(o[ns][0] * inv0, o[ns][1] * inv0);
        *(__half2*)(g_Ah + (size_t)(row + 8) * HIDN + col) =
            __floats2half2_rn(o[ns][2] * inv1, o[ns][3] * inv1);
    }
}

// ---------------------------------------------------------------------------
extern "C" void kernel_launch(void* const* d_in, const int* in_sizes, int n_in,
                              void* d_out, int out_size)
{
    const float* X  = (const float*)d_in[0];
    const float* Wq = (const float*)d_in[2];
    const float* Wk = (const float*)d_in[3];
    const float* Wv = (const float*)d_in[4];
    const float* Wo = (const float*)d_in[5];
    float* out = (float*)d_out;

    float *dQ, *dK, *dV;
    cudaGetSymbolAddress((void**)&dQ, g_Q);
    cudaGetSymbolAddress((void**)&dK, g_K);
    cudaGetSymbolAddress((void**)&dV, g_V);
    __half *xh, *ah, *qh, *ql, *kh, *kl, *vh, *vl, *oh, *ol;
    cudaGetSymbolAddress((void**)&xh, g_Xh);
    cudaGetSymbolAddress((void**)&ah, g_Ah);
    cudaGetSymbolAddress((void**)&qh, g_Wqh); cudaGetSymbolAddress((void**)&ql, g_Wql);
    cudaGetSymbolAddress((void**)&kh, g_Wkh); cudaGetSymbolAddress((void**)&kl, g_Wkl);
    cudaGetSymbolAddress((void**)&vh, g_Wvh); cudaGetSymbolAddress((void**)&vl, g_Wvl);
    cudaGetSymbolAddress((void**)&oh, g_Woh); cudaGetSymbolAddress((void**)&ol, g_Wol);

    rope_table<<<(S_LEN * 64) / 256, 256>>>();

    const int nX4 = S_LEN * HIDN / 4, nW4 = HIDN * HIDN / 4;
    split_round<<<nX4 / 256, 256>>>(X, xh);
    split_hilo<<<nW4 / 256, 256>>>(Wq, qh, ql);
    split_hilo<<<nW4 / 256, 256>>>(Wk, kh, kl);
    split_hilo<<<nW4 / 256, 256>>>(Wv, vh, vl);
    split_hilo<<<nW4 / 256, 256>>>(Wo, oh, ol);

    cudaFuncSetAttribute(gemm_f16, cudaFuncAttributeMaxDynamicSharedMemorySize, GEMM_SMEM);
    const dim3 gg(HIDN / 128, S_LEN / 128);
    gemm_f16<<<gg, 128, GEMM_SMEM>>>(xh, qh, ql, dQ);
    gemm_f16<<<gg, 128, GEMM_SMEM>>>(xh, kh, kl, dK);
    gemm_f16<<<gg, 128, GEMM_SMEM>>>(xh, vh, vl, dV);

    rope_split<<<(S_LEN * NHEAD * 64) / 256, 256>>>();
    vt_split<<<(NHEAD * HDIM * S_LEN) / 256, 256>>>();

    cudaFuncSetAttribute(flash_mma, cudaFuncAttributeMaxDynamicSharedMemorySize, FLASH_SMEM_B);
    flash_mma<<<dim3(S_LEN / 128, NHEAD), 256, FLASH_SMEM_B>>>();

    gemm_f16<<<gg, 128, GEMM_SMEM>>>(ah, oh, ol, out);
}